// round 8
// baseline (speedup 1.0000x reference)
#include <cuda_runtime.h>
#include <cstdint>
#include <cstddef>

#define BB 8
#define LL 2048
#define HH 8
#define DD 64
#define EE 33
#define UU 40
#define SK 40
#define BHN (BB*HH)
#define ROWS (BHN*LL)

// ---------------- static scratch ----------------
__device__ float2 g_qf [ROWS*EE];
__device__ float2 g_kf [ROWS*EE];
__device__ float2 g_vf [ROWS*EE];
__device__ float2 g_kfT[ROWS*EE];
__device__ float4 g_kfC[(size_t)BHN*8*4096];
__device__ float  g_k32[BHN*LL];
__device__ float  g_M  [ROWS];
__device__ int    g_top [BHN*UU];
__device__ int    g_slot[ROWS];
__device__ float2 g_upd [BHN*UU*EE];
__device__ float  g_vmt[BHN*DD];

__device__ __forceinline__ void cpa16(void* s, const void* g) {
    unsigned sa = (unsigned)__cvta_generic_to_shared(s);
    asm volatile("cp.async.cg.shared.global [%0], [%1], 16;" :: "r"(sa), "l"(g));
}
__device__ __forceinline__ void cp_commit() {
    asm volatile("cp.async.commit_group;" ::: "memory");
}
__device__ __forceinline__ void cp_wait1() {
    asm volatile("cp.async.wait_group 1;" ::: "memory");
}
__device__ __forceinline__ void cp_wait0() {
    asm volatile("cp.async.wait_group 0;" ::: "memory");
}

// ---------------- K1: rfft, shfl butterfly with smem twiddle LUTs ----------------
__global__ void k_rfft(const float* __restrict__ q,
                       const float* __restrict__ k,
                       const float* __restrict__ v)
{
    __shared__ float2 w32t[16], w64t[32];
    __shared__ float2 zs[8][32];
    int tid = threadIdx.x;
    if (tid < 16) {
        float s, c;
        sincospif(tid * (1.0f/16.0f), &s, &c);
        w32t[tid] = make_float2(c, s);
    } else if (tid < 48) {
        float s, c;
        sincospif((tid - 16) * (1.0f/32.0f), &s, &c);
        w64t[tid - 16] = make_float2(c, s);
    }
    __syncthreads();
    int warp = tid >> 5, lane = tid & 31;
    int r  = blockIdx.x * 8 + warp;
    int l  = r & (LL - 1);
    int bh = r >> 11;
    int b = bh >> 3, h = bh & 7;
    const float* src = (blockIdx.y == 0) ? q : (blockIdx.y == 1) ? k : v;
    const float2* x2 = (const float2*)(src + (((size_t)b*LL + l)*HH + h) * DD);
    float2 z = x2[lane];
    float zr = z.x, zi = z.y;
    #pragma unroll
    for (int s = 0; s < 5; ++s) {
        int hm = 16 >> s;
        float orr = __shfl_xor_sync(0xffffffffu, zr, hm);
        float oii = __shfl_xor_sync(0xffffffffu, zi, hm);
        float2 w = w32t[(lane & (hm - 1)) << s];
        float dx = orr - zr, dy = oii - zi;
        float hr = dx*w.x + dy*w.y;
        float hi = dy*w.x - dx*w.y;
        float lr = zr + orr, li = zi + oii;
        bool top = (lane & hm) != 0;
        zr = top ? hr : lr;
        zi = top ? hi : li;
    }
    int bin = __brev((unsigned)lane) >> 27;
    zs[warp][bin] = make_float2(zr, zi);
    __syncwarp();
    float2 m = zs[warp][(32 - bin) & 31];
    float Zer = 0.5f*(zr + m.x), Zei = 0.5f*(zi - m.y);
    float Zor = 0.5f*(zi + m.y), Zoi = -0.5f*(zr - m.x);
    float2 w = w64t[bin];
    float Xr = Zer + w.x*Zor + w.y*Zoi;
    float Xi = Zei + w.x*Zoi - w.y*Zor;
    float2* out = (blockIdx.y == 0) ? g_qf : (blockIdx.y == 1) ? g_kf : g_vf;
    out[(size_t)r*EE + bin] = make_float2(Xr, Xi);
    if (bin == 0) out[(size_t)r*EE + 32] = make_float2(zr - zi, 0.f);
}

// ---------------- K2: transpose k_fft -> e-major + chunked row-major ----------------
__global__ void k_transpose()
{
    __shared__ float2 tile[32][EE];
    int bh = blockIdx.y;
    int l0 = blockIdx.x * 32;
    for (int t = threadIdx.x; t < 32*EE; t += 256) {
        int r = t / EE, e = t - r*EE;
        tile[r][e] = g_kf[((size_t)bh*LL + l0 + r)*EE + e];
    }
    __syncthreads();
    for (int t = threadIdx.x; t < EE*32; t += 256) {
        int e = t >> 5, r = t & 31;
        g_kfT[((size_t)bh*EE + e)*LL + l0 + r] = tile[r][e];
    }
    for (int t = threadIdx.x; t < 512; t += 256) {
        int half = t >> 8;
        int c    = (t >> 5) & 7;
        int r    = t & 31;
        float2 a = tile[r][c*4 + half*2];
        float2 b = tile[r][c*4 + half*2 + 1];
        g_kfC[(((size_t)(bh*8 + c)) << 12) + (size_t)(l0 + r)*2 + half] =
            make_float4(a.x, a.y, b.x, b.y);
    }
    if (threadIdx.x < 32)
        g_k32[bh*LL + l0 + threadIdx.x] = tile[threadIdx.x][32].x;
}

// ---------------- K2b: time-domain v mean ----------------
__global__ void k_vmt(const float* __restrict__ v)
{
    __shared__ float part[8][64];
    int bh = blockIdx.x, b = bh >> 3, h = bh & 7;
    int tid = threadIdx.x;
    int d = tid & 63, g = tid >> 6;
    const float* base = v + (((size_t)b*LL)*HH + h) * DD + d;
    float acc = 0.f;
    #pragma unroll 8
    for (int i = g; i < LL; i += 8) acc += base[(size_t)i * (HH*DD)];
    part[g][d] = acc;
    __syncthreads();
    if (tid < 64) {
        float s = 0.f;
        #pragma unroll
        for (int g2 = 0; g2 < 8; ++g2) s += part[g2][tid];
        g_vmt[bh*DD + tid] = s * (1.0f/LL);
    }
}

// ---------------- K3: sampled QK -> M ----------------
#define MS_SMEM (131072 + 8192 + 16384)
__global__ void __launch_bounds__(1024, 1) k_msample(const int* __restrict__ isamp)
{
    extern __shared__ char sm[];
    float4* kbuf = (float4*)sm;
    float*  sk32 = (float*)(sm + 131072);
    float4* pt   = (float4*)(sm + 131072 + 8192);

    int tid = threadIdx.x;
    int l0  = blockIdx.x * 256;
    int bh  = blockIdx.y;
    int sg  = tid & 3;
    int lq  = tid >> 2;
    int l   = l0 + lq;

    sk32[tid]        = g_k32[bh*LL + tid];
    sk32[tid + 1024] = g_k32[bh*LL + tid + 1024];

    const int* ip = isamp + l*SK + sg*10;
    int ids[10];
    #pragma unroll
    for (int i = 0; i < 10; ++i) ids[i] = ip[i];

    const float4* kc = g_kfC + (((size_t)(bh*8)) << 12);
    #pragma unroll
    for (int it = 0; it < 4; ++it) {
        int lin = it*1024 + tid;
        int sw  = lin ^ ((lin >> 3) & 7);
        cpa16(&kbuf[sw], &kc[lin]);
    }
    cp_commit();

    float accR[10], accI[10];
    #pragma unroll
    for (int s = 0; s < 10; ++s) { accR[s] = 0.f; accI[s] = 0.f; }
    const float2* qrow = g_qf + (size_t)(bh*LL + l)*EE;

    #pragma unroll 1
    for (int c = 0; c < 8; ++c) {
        int cur = (c & 1) << 12;
        if (c < 7) {
            const float4* src = kc + ((size_t)(c+1) << 12);
            int nb = ((c+1) & 1) << 12;
            #pragma unroll
            for (int it = 0; it < 4; ++it) {
                int lin = it*1024 + tid;
                int sw  = lin ^ ((lin >> 3) & 7);
                cpa16(&kbuf[nb + sw], &src[lin]);
            }
            cp_commit();
            cp_wait1();
        } else {
            cp_wait0();
        }
        __syncthreads();
        float2 q0 = qrow[4*c], q1 = qrow[4*c+1], q2 = qrow[4*c+2], q3 = qrow[4*c+3];
        #pragma unroll
        for (int s = 0; s < 10; ++s) {
            int id = ids[s];
            int p = id << 1, x = (id >> 2) & 7;
            float4 h0 = kbuf[cur + (p ^ x)];
            float4 h1 = kbuf[cur + ((p + 1) ^ x)];
            accR[s] = fmaf(q0.x, h0.x, accR[s]); accR[s] = fmaf(-q0.y, h0.y, accR[s]);
            accI[s] = fmaf(q0.x, h0.y, accI[s]); accI[s] = fmaf( q0.y, h0.x, accI[s]);
            accR[s] = fmaf(q1.x, h0.z, accR[s]); accR[s] = fmaf(-q1.y, h0.w, accR[s]);
            accI[s] = fmaf(q1.x, h0.w, accI[s]); accI[s] = fmaf( q1.y, h0.z, accI[s]);
            accR[s] = fmaf(q2.x, h1.x, accR[s]); accR[s] = fmaf(-q2.y, h1.y, accR[s]);
            accI[s] = fmaf(q2.x, h1.y, accI[s]); accI[s] = fmaf( q2.y, h1.x, accI[s]);
            accR[s] = fmaf(q3.x, h1.z, accR[s]); accR[s] = fmaf(-q3.y, h1.w, accR[s]);
            accI[s] = fmaf(q3.x, h1.w, accI[s]); accI[s] = fmaf( q3.y, h1.z, accI[s]);
        }
        __syncthreads();
    }
    {
        float q32 = qrow[32].x;
        #pragma unroll
        for (int s = 0; s < 10; ++s)
            accR[s] = fmaf(q32, sk32[ids[s]], accR[s]);
    }
    float mr = -3.4e38f, mi = -3.4e38f, sr = 0.f, si = 0.f;
    #pragma unroll
    for (int s = 0; s < 10; ++s) {
        mr = fmaxf(mr, accR[s]); mi = fmaxf(mi, accI[s]);
        sr += accR[s];           si += accI[s];
    }
    pt[sg*256 + lq] = make_float4(mr, mi, sr, si);
    __syncthreads();
    if (tid < 256) {
        float4 a = pt[tid], b = pt[256 + tid], c2 = pt[512 + tid], d = pt[768 + tid];
        float MR = fmaxf(fmaxf(a.x, b.x), fmaxf(c2.x, d.x));
        float MI = fmaxf(fmaxf(a.y, b.y), fmaxf(c2.y, d.y));
        float SR = a.z + b.z + c2.z + d.z;
        float SI = a.w + b.w + c2.w + d.w;
        g_M[(size_t)bh*LL + l0 + tid] = MR + MI - (SR + SI) * (1.0f/LL);
    }
}

// ---------------- K4: top-40 per bh ----------------
__global__ void k_topk()
{
    __shared__ float mv[LL];
    __shared__ float wv[8];
    __shared__ int   wi[8];
    int bh = blockIdx.x, tid = threadIdx.x, lane = tid & 31, warp = tid >> 5;
    for (int i = tid; i < LL; i += 256) {
        mv[i] = g_M[bh*LL + i];
        g_slot[bh*LL + i] = -1;
    }
    __syncthreads();
    for (int u = 0; u < UU; ++u) {
        float best = -3.4e38f; int bi = 1 << 30;
        for (int i = tid; i < LL; i += 256) {
            float x = mv[i];
            if (x > best) { best = x; bi = i; }
        }
        #pragma unroll
        for (int o = 16; o; o >>= 1) {
            float ov = __shfl_xor_sync(0xffffffffu, best, o);
            int   oi = __shfl_xor_sync(0xffffffffu, bi, o);
            if (ov > best || (ov == best && oi < bi)) { best = ov; bi = oi; }
        }
        if (lane == 0) { wv[warp] = best; wi[warp] = bi; }
        __syncthreads();
        if (warp == 0) {
            float b2 = (lane < 8) ? wv[lane] : -3.4e38f;
            int   i2 = (lane < 8) ? wi[lane] : (1 << 30);
            #pragma unroll
            for (int o = 4; o; o >>= 1) {
                float ov = __shfl_xor_sync(0xffffffffu, b2, o);
                int   oi = __shfl_xor_sync(0xffffffffu, i2, o);
                if (ov > b2 || (ov == b2 && oi < i2)) { b2 = ov; i2 = oi; }
            }
            if (lane == 0) {
                g_top[bh*UU + u] = i2;
                g_slot[bh*LL + i2] = u;
                mv[i2] = -3.4e38f;
            }
        }
        __syncthreads();
    }
}

// ---------------- K5: fused scores + softmax + upd (8 u per block) ----------------
#define FS_SMEM (131072 + 2112 + 33792 + 256)
__global__ void __launch_bounds__(512, 1) k_fused()
{
    extern __shared__ char smc[];
    float2* p    = (float2*)smc;                           // [8][2048] scores->probs
    float2* shq  = (float2*)(smc + 131072);                // [8][33]
    float2* accs = (float2*)(smc + 131072 + 2112);         // [16][8][33]
    float2* red  = (float2*)(smc + 131072 + 2112 + 33792); // [16]
    int bh = blockIdx.y, ug = blockIdx.x;
    int tid = threadIdx.x, warp = tid >> 5, lane = tid & 31;

    // stage 8 selected q rows
    for (int t = tid; t < 8*EE; t += 512) {
        int u = t / EE, e = t - u*EE;
        int qi = g_top[bh*UU + ug*8 + u];
        shq[u*EE + e] = g_qf[((size_t)bh*LL + qi)*EE + e];
    }
    __syncthreads();

    // ---- scores: 2 passes, 2 j's per thread per pass ----
    const float2* kT = g_kfT + (size_t)bh*EE*LL;
    const float sc = 0.125f;
    #pragma unroll 1
    for (int pass = 0; pass < 2; ++pass) {
        int j0 = pass*1024 + tid;
        float aR0[8], aI0[8], aR1[8], aI1[8];
        #pragma unroll
        for (int u = 0; u < 8; ++u) { aR0[u]=aI0[u]=aR1[u]=aI1[u]=0.f; }
        for (int e = 0; e < EE; ++e) {
            float2 k0 = kT[(size_t)e*LL + j0];
            float2 k1 = kT[(size_t)e*LL + j0 + 512];
            #pragma unroll
            for (int u = 0; u < 8; ++u) {
                float2 qv = shq[u*EE + e];
                aR0[u] = fmaf(qv.x, k0.x, aR0[u]); aR0[u] = fmaf(-qv.y, k0.y, aR0[u]);
                aI0[u] = fmaf(qv.x, k0.y, aI0[u]); aI0[u] = fmaf( qv.y, k0.x, aI0[u]);
                aR1[u] = fmaf(qv.x, k1.x, aR1[u]); aR1[u] = fmaf(-qv.y, k1.y, aR1[u]);
                aI1[u] = fmaf(qv.x, k1.y, aI1[u]); aI1[u] = fmaf( qv.y, k1.x, aI1[u]);
            }
        }
        #pragma unroll
        for (int u = 0; u < 8; ++u) {
            p[(u << 11) + j0]       = make_float2(aR0[u]*sc, aI0[u]*sc);
            p[(u << 11) + j0 + 512] = make_float2(aR1[u]*sc, aI1[u]*sc);
        }
    }
    __syncthreads();

    // ---- softmax: warp w -> row u = w>>1, half = w&1 ----
    int su = warp >> 1, half = warp & 1;
    float2* row = p + (su << 11) + (half << 10);
    float mr = -3.4e38f, mi = -3.4e38f;
    #pragma unroll 8
    for (int k2 = 0; k2 < 32; ++k2) {
        float2 vv = row[lane + k2*32];
        mr = fmaxf(mr, vv.x); mi = fmaxf(mi, vv.y);
    }
    #pragma unroll
    for (int o = 16; o; o >>= 1) {
        mr = fmaxf(mr, __shfl_xor_sync(0xffffffffu, mr, o));
        mi = fmaxf(mi, __shfl_xor_sync(0xffffffffu, mi, o));
    }
    if (lane == 0) red[warp] = make_float2(mr, mi);
    __syncthreads();
    {
        float2 a = red[su*2], b = red[su*2+1];
        mr = fmaxf(a.x, b.x); mi = fmaxf(a.y, b.y);
    }
    __syncthreads();
    float sr = 0.f, si = 0.f;
    #pragma unroll 8
    for (int k2 = 0; k2 < 32; ++k2) {
        float2 vv = row[lane + k2*32];
        float er = __expf(vv.x - mr);
        float ei = __expf(vv.y - mi);
        row[lane + k2*32] = make_float2(er, ei);
        sr += er; si += ei;
    }
    #pragma unroll
    for (int o = 16; o; o >>= 1) {
        sr += __shfl_xor_sync(0xffffffffu, sr, o);
        si += __shfl_xor_sync(0xffffffffu, si, o);
    }
    if (lane == 0) red[warp] = make_float2(sr, si);
    __syncthreads();
    {
        float2 a = red[su*2], b = red[su*2+1];
        float inr = 1.0f / (a.x + b.x);
        float ini = 1.0f / (a.y + b.y);
        #pragma unroll 8
        for (int k2 = 0; k2 < 32; ++k2) {
            float2 vv = row[lane + k2*32];
            row[lane + k2*32] = make_float2(vv.x * inr, vv.y * ini);
        }
    }
    __syncthreads();

    // ---- upd: warp-strided over l, lane = e ----
    float aR[8], aI[8], aR2[8], aI2[8];
    #pragma unroll
    for (int u = 0; u < 8; ++u) { aR[u]=aI[u]=aR2[u]=aI2[u]=0.f; }
    const float2* vb = g_vf + (size_t)bh*LL*EE;
    for (int l = warp; l < LL; l += 16) {
        float2 v2 = vb[(size_t)l*EE + lane];
        float2 v32 = make_float2(0.f, 0.f);
        if (lane == 0) v32 = vb[(size_t)l*EE + 32];
        #pragma unroll
        for (int u = 0; u < 8; ++u) {
            float2 pp = p[(u << 11) + l];
            aR[u]  = fmaf(pp.x, v2.x,  aR[u]);
            aI[u]  = fmaf(pp.y, v2.y,  aI[u]);
            aR2[u] = fmaf(pp.x, v32.x, aR2[u]);
            aI2[u] = fmaf(pp.y, v32.y, aI2[u]);
        }
    }
    #pragma unroll
    for (int u = 0; u < 8; ++u) {
        accs[(warp*8 + u)*EE + lane] = make_float2(aR[u], aI[u]);
        if (lane == 0) accs[(warp*8 + u)*EE + 32] = make_float2(aR2[u], aI2[u]);
    }
    __syncthreads();
    for (int t = tid; t < 8*EE; t += 512) {
        int u = t / EE, e = t - u*EE;
        float ssr = 0.f, ssi = 0.f;
        #pragma unroll
        for (int w = 0; w < 16; ++w) {
            float2 a = accs[(w*8 + u)*EE + e];
            ssr += a.x; ssi += a.y;
        }
        g_upd[((size_t)bh*UU + ug*8 + u)*EE + e] = make_float2(ssr, ssi);
    }
}

// ---------------- K7: scatter + irfft of selected rows ----------------
__global__ void k_out(float* __restrict__ out)
{
    __shared__ float tc[64], ts[64];
    __shared__ float2 ub[8][EE];
    int tid = threadIdx.x;
    if (tid < 64) {
        float s, c;
        sincospif(tid * (1.0f/32.0f), &s, &c);
        tc[tid] = c; ts[tid] = s;
    }
    __syncthreads();
    int warp = tid >> 5, lane = tid & 31;
    int r = blockIdx.x * 8 + warp;
    int bh = r >> 11;
    int slot = g_slot[r];
    float* op = out + (size_t)r * DD;
    if (slot < 0) {
        op[lane]      = g_vmt[bh*DD + lane];
        op[lane + 32] = g_vmt[bh*DD + lane + 32];
    } else {
        const float2* X = g_upd + ((size_t)bh*UU + slot)*EE;
        ub[warp][lane] = X[lane];
        if (lane == 0) ub[warp][32] = X[32];
        __syncwarp();
        float a0 = ub[warp][0].x;
        float a32 = ub[warp][32].x;
        float sgn = (lane & 1) ? -a32 : a32;
        float acc1 = a0 + sgn, acc2 = a0 + sgn;
        #pragma unroll
        for (int e = 1; e < 32; ++e) {
            float2 Xe = ub[warp][e];
            int j1 = (e * lane) & 63;
            int j2 = (e * (lane + 32)) & 63;
            acc1 += 2.f * (Xe.x*tc[j1] - Xe.y*ts[j1]);
            acc2 += 2.f * (Xe.x*tc[j2] - Xe.y*ts[j2]);
        }
        op[lane]      = acc1 * (1.0f/64.0f);
        op[lane + 32] = acc2 * (1.0f/64.0f);
    }
}

// ---------------- launch ----------------
extern "C" void kernel_launch(void* const* d_in, const int* in_sizes, int n_in,
                              void* d_out, int out_size)
{
    (void)in_sizes; (void)n_in; (void)out_size;
    const float* q = (const float*)d_in[0];
    const float* k = (const float*)d_in[1];
    const float* v = (const float*)d_in[2];
    const int* isamp = (const int*)d_in[4];
    float* out = (float*)d_out;

    cudaFuncSetAttribute(k_msample, cudaFuncAttributeMaxDynamicSharedMemorySize, MS_SMEM);
    cudaFuncSetAttribute(k_fused,   cudaFuncAttributeMaxDynamicSharedMemorySize, FS_SMEM);

    k_rfft     <<<dim3(ROWS/8, 3), 256>>>(q, k, v);
    k_transpose<<<dim3(LL/32, BHN), 256>>>();
    k_vmt      <<<BHN, 512>>>(v);
    k_msample  <<<dim3(LL/256, BHN), 1024, MS_SMEM>>>(isamp);
    k_topk     <<<BHN, 256>>>();
    k_fused    <<<dim3(5, BHN), 512, FS_SMEM>>>();
    k_out      <<<ROWS/8, 256>>>(out);
}

// round 9
// speedup vs baseline: 1.1412x; 1.1412x over previous
#include <cuda_runtime.h>
#include <cstdint>
#include <cstddef>

#define BB 8
#define LL 2048
#define HH 8
#define DD 64
#define EE 33
#define UU 40
#define SK 40
#define BHN (BB*HH)
#define ROWS (BHN*LL)

// ---------------- static scratch ----------------
__device__ float2 g_qf [ROWS*EE];
__device__ float2 g_kf [ROWS*EE];
__device__ float2 g_vf [ROWS*EE];
__device__ float2 g_kfT[ROWS*EE];
__device__ float4 g_kfC[(size_t)BHN*8*4096];
__device__ float  g_k32[BHN*LL];
__device__ float  g_M  [ROWS];
__device__ int    g_top [BHN*UU];
__device__ int    g_slot[ROWS];
__device__ float2 g_upd [BHN*UU*EE];
__device__ float  g_vmt[BHN*DD];
__device__ float2 g_big [(size_t)BHN*UU*LL];

__device__ __forceinline__ void cpa16(void* s, const void* g) {
    unsigned sa = (unsigned)__cvta_generic_to_shared(s);
    asm volatile("cp.async.cg.shared.global [%0], [%1], 16;" :: "r"(sa), "l"(g));
}
__device__ __forceinline__ void cp_commit() {
    asm volatile("cp.async.commit_group;" ::: "memory");
}
__device__ __forceinline__ void cp_wait1() {
    asm volatile("cp.async.wait_group 1;" ::: "memory");
}
__device__ __forceinline__ void cp_wait0() {
    asm volatile("cp.async.wait_group 0;" ::: "memory");
}

// ---------------- K1: rfft, shfl butterfly with smem twiddle LUTs ----------------
__global__ void k_rfft(const float* __restrict__ q,
                       const float* __restrict__ k,
                       const float* __restrict__ v)
{
    __shared__ float2 w32t[16], w64t[32];
    __shared__ float2 zs[8][32];
    int tid = threadIdx.x;
    if (tid < 16) {
        float s, c;
        sincospif(tid * (1.0f/16.0f), &s, &c);
        w32t[tid] = make_float2(c, s);
    } else if (tid < 48) {
        float s, c;
        sincospif((tid - 16) * (1.0f/32.0f), &s, &c);
        w64t[tid - 16] = make_float2(c, s);
    }
    __syncthreads();
    int warp = tid >> 5, lane = tid & 31;
    int r  = blockIdx.x * 8 + warp;
    int l  = r & (LL - 1);
    int bh = r >> 11;
    int b = bh >> 3, h = bh & 7;
    const float* src = (blockIdx.y == 0) ? q : (blockIdx.y == 1) ? k : v;
    const float2* x2 = (const float2*)(src + (((size_t)b*LL + l)*HH + h) * DD);
    float2 z = x2[lane];
    float zr = z.x, zi = z.y;
    #pragma unroll
    for (int s = 0; s < 5; ++s) {
        int hm = 16 >> s;
        float orr = __shfl_xor_sync(0xffffffffu, zr, hm);
        float oii = __shfl_xor_sync(0xffffffffu, zi, hm);
        float2 w = w32t[(lane & (hm - 1)) << s];
        float dx = orr - zr, dy = oii - zi;
        float hr = dx*w.x + dy*w.y;
        float hi = dy*w.x - dx*w.y;
        float lr = zr + orr, li = zi + oii;
        bool top = (lane & hm) != 0;
        zr = top ? hr : lr;
        zi = top ? hi : li;
    }
    int bin = __brev((unsigned)lane) >> 27;
    zs[warp][bin] = make_float2(zr, zi);
    __syncwarp();
    float2 m = zs[warp][(32 - bin) & 31];
    float Zer = 0.5f*(zr + m.x), Zei = 0.5f*(zi - m.y);
    float Zor = 0.5f*(zi + m.y), Zoi = -0.5f*(zr - m.x);
    float2 w = w64t[bin];
    float Xr = Zer + w.x*Zor + w.y*Zoi;
    float Xi = Zei + w.x*Zoi - w.y*Zor;
    float2* out = (blockIdx.y == 0) ? g_qf : (blockIdx.y == 1) ? g_kf : g_vf;
    out[(size_t)r*EE + bin] = make_float2(Xr, Xi);
    if (bin == 0) out[(size_t)r*EE + 32] = make_float2(zr - zi, 0.f);
}

// ---------------- K2: transpose k_fft -> e-major + chunked row-major ----------------
__global__ void k_transpose()
{
    __shared__ float2 tile[32][EE];
    int bh = blockIdx.y;
    int l0 = blockIdx.x * 32;
    for (int t = threadIdx.x; t < 32*EE; t += 256) {
        int r = t / EE, e = t - r*EE;
        tile[r][e] = g_kf[((size_t)bh*LL + l0 + r)*EE + e];
    }
    __syncthreads();
    for (int t = threadIdx.x; t < EE*32; t += 256) {
        int e = t >> 5, r = t & 31;
        g_kfT[((size_t)bh*EE + e)*LL + l0 + r] = tile[r][e];
    }
    for (int t = threadIdx.x; t < 512; t += 256) {
        int half = t >> 8;
        int c    = (t >> 5) & 7;
        int r    = t & 31;
        float2 a = tile[r][c*4 + half*2];
        float2 b = tile[r][c*4 + half*2 + 1];
        g_kfC[(((size_t)(bh*8 + c)) << 12) + (size_t)(l0 + r)*2 + half] =
            make_float4(a.x, a.y, b.x, b.y);
    }
    if (threadIdx.x < 32)
        g_k32[bh*LL + l0 + threadIdx.x] = tile[threadIdx.x][32].x;
}

// ---------------- K2b: time-domain v mean ----------------
__global__ void k_vmt(const float* __restrict__ v)
{
    __shared__ float part[8][64];
    int bh = blockIdx.x, b = bh >> 3, h = bh & 7;
    int tid = threadIdx.x;
    int d = tid & 63, g = tid >> 6;
    const float* base = v + (((size_t)b*LL)*HH + h) * DD + d;
    float acc = 0.f;
    #pragma unroll 8
    for (int i = g; i < LL; i += 8) acc += base[(size_t)i * (HH*DD)];
    part[g][d] = acc;
    __syncthreads();
    if (tid < 64) {
        float s = 0.f;
        #pragma unroll
        for (int g2 = 0; g2 < 8; ++g2) s += part[g2][tid];
        g_vmt[bh*DD + tid] = s * (1.0f/LL);
    }
}

// ---------------- K3: sampled QK -> M ----------------
#define MS_SMEM (131072 + 8192 + 16384)
__global__ void __launch_bounds__(1024, 1) k_msample(const int* __restrict__ isamp)
{
    extern __shared__ char sm[];
    float4* kbuf = (float4*)sm;
    float*  sk32 = (float*)(sm + 131072);
    float4* pt   = (float4*)(sm + 131072 + 8192);

    int tid = threadIdx.x;
    int l0  = blockIdx.x * 256;
    int bh  = blockIdx.y;
    int sg  = tid & 3;
    int lq  = tid >> 2;
    int l   = l0 + lq;

    sk32[tid]        = g_k32[bh*LL + tid];
    sk32[tid + 1024] = g_k32[bh*LL + tid + 1024];

    const int* ip = isamp + l*SK + sg*10;
    int ids[10];
    #pragma unroll
    for (int i = 0; i < 10; ++i) ids[i] = ip[i];

    const float4* kc = g_kfC + (((size_t)(bh*8)) << 12);
    #pragma unroll
    for (int it = 0; it < 4; ++it) {
        int lin = it*1024 + tid;
        int sw  = lin ^ ((lin >> 3) & 7);
        cpa16(&kbuf[sw], &kc[lin]);
    }
    cp_commit();

    float accR[10], accI[10];
    #pragma unroll
    for (int s = 0; s < 10; ++s) { accR[s] = 0.f; accI[s] = 0.f; }
    const float2* qrow = g_qf + (size_t)(bh*LL + l)*EE;

    #pragma unroll 1
    for (int c = 0; c < 8; ++c) {
        int cur = (c & 1) << 12;
        if (c < 7) {
            const float4* src = kc + ((size_t)(c+1) << 12);
            int nb = ((c+1) & 1) << 12;
            #pragma unroll
            for (int it = 0; it < 4; ++it) {
                int lin = it*1024 + tid;
                int sw  = lin ^ ((lin >> 3) & 7);
                cpa16(&kbuf[nb + sw], &src[lin]);
            }
            cp_commit();
            cp_wait1();
        } else {
            cp_wait0();
        }
        __syncthreads();
        float2 q0 = qrow[4*c], q1 = qrow[4*c+1], q2 = qrow[4*c+2], q3 = qrow[4*c+3];
        #pragma unroll
        for (int s = 0; s < 10; ++s) {
            int id = ids[s];
            int p = id << 1, x = (id >> 2) & 7;
            float4 h0 = kbuf[cur + (p ^ x)];
            float4 h1 = kbuf[cur + ((p + 1) ^ x)];
            accR[s] = fmaf(q0.x, h0.x, accR[s]); accR[s] = fmaf(-q0.y, h0.y, accR[s]);
            accI[s] = fmaf(q0.x, h0.y, accI[s]); accI[s] = fmaf( q0.y, h0.x, accI[s]);
            accR[s] = fmaf(q1.x, h0.z, accR[s]); accR[s] = fmaf(-q1.y, h0.w, accR[s]);
            accI[s] = fmaf(q1.x, h0.w, accI[s]); accI[s] = fmaf( q1.y, h0.z, accI[s]);
            accR[s] = fmaf(q2.x, h1.x, accR[s]); accR[s] = fmaf(-q2.y, h1.y, accR[s]);
            accI[s] = fmaf(q2.x, h1.y, accI[s]); accI[s] = fmaf( q2.y, h1.x, accI[s]);
            accR[s] = fmaf(q3.x, h1.z, accR[s]); accR[s] = fmaf(-q3.y, h1.w, accR[s]);
            accI[s] = fmaf(q3.x, h1.w, accI[s]); accI[s] = fmaf( q3.y, h1.z, accI[s]);
        }
        __syncthreads();
    }
    {
        float q32 = qrow[32].x;
        #pragma unroll
        for (int s = 0; s < 10; ++s)
            accR[s] = fmaf(q32, sk32[ids[s]], accR[s]);
    }
    float mr = -3.4e38f, mi = -3.4e38f, sr = 0.f, si = 0.f;
    #pragma unroll
    for (int s = 0; s < 10; ++s) {
        mr = fmaxf(mr, accR[s]); mi = fmaxf(mi, accI[s]);
        sr += accR[s];           si += accI[s];
    }
    pt[sg*256 + lq] = make_float4(mr, mi, sr, si);
    __syncthreads();
    if (tid < 256) {
        float4 a = pt[tid], b = pt[256 + tid], c2 = pt[512 + tid], d = pt[768 + tid];
        float MR = fmaxf(fmaxf(a.x, b.x), fmaxf(c2.x, d.x));
        float MI = fmaxf(fmaxf(a.y, b.y), fmaxf(c2.y, d.y));
        float SR = a.z + b.z + c2.z + d.z;
        float SI = a.w + b.w + c2.w + d.w;
        g_M[(size_t)bh*LL + l0 + tid] = MR + MI - (SR + SI) * (1.0f/LL);
    }
}

// ---------------- K4: top-40 per bh ----------------
__global__ void k_topk()
{
    __shared__ float mv[LL];
    __shared__ float wv[8];
    __shared__ int   wi[8];
    int bh = blockIdx.x, tid = threadIdx.x, lane = tid & 31, warp = tid >> 5;
    for (int i = tid; i < LL; i += 256) {
        mv[i] = g_M[bh*LL + i];
        g_slot[bh*LL + i] = -1;
    }
    __syncthreads();
    for (int u = 0; u < UU; ++u) {
        float best = -3.4e38f; int bi = 1 << 30;
        for (int i = tid; i < LL; i += 256) {
            float x = mv[i];
            if (x > best) { best = x; bi = i; }
        }
        #pragma unroll
        for (int o = 16; o; o >>= 1) {
            float ov = __shfl_xor_sync(0xffffffffu, best, o);
            int   oi = __shfl_xor_sync(0xffffffffu, bi, o);
            if (ov > best || (ov == best && oi < bi)) { best = ov; bi = oi; }
        }
        if (lane == 0) { wv[warp] = best; wi[warp] = bi; }
        __syncthreads();
        if (warp == 0) {
            float b2 = (lane < 8) ? wv[lane] : -3.4e38f;
            int   i2 = (lane < 8) ? wi[lane] : (1 << 30);
            #pragma unroll
            for (int o = 4; o; o >>= 1) {
                float ov = __shfl_xor_sync(0xffffffffu, b2, o);
                int   oi = __shfl_xor_sync(0xffffffffu, i2, o);
                if (ov > b2 || (ov == b2 && oi < i2)) { b2 = ov; i2 = oi; }
            }
            if (lane == 0) {
                g_top[bh*UU + u] = i2;
                g_slot[bh*LL + i2] = u;
                mv[i2] = -3.4e38f;
            }
        }
        __syncthreads();
    }
}

// ---------------- K5: full scores, 20-u register blocked ----------------
__global__ void __launch_bounds__(512) k_scores()
{
    __shared__ float2 shq[20][EE];
    int bh = blockIdx.z;
    int ug = blockIdx.y;
    int jt = blockIdx.x;
    int tid = threadIdx.x;
    for (int t = tid; t < 20*EE; t += 512) {
        int ul = t / EE, e = t - ul*EE;
        int qi = g_top[bh*UU + ug*20 + ul];
        shq[ul][e] = g_qf[((size_t)bh*LL + qi)*EE + e];
    }
    __syncthreads();
    int j = jt*512 + tid;
    float accR[20], accI[20];
    #pragma unroll
    for (int u = 0; u < 20; ++u) { accR[u] = 0.f; accI[u] = 0.f; }
    const float2* kT = g_kfT + (size_t)bh*EE*LL + j;
    for (int e = 0; e < 32; ++e) {
        float2 kv = kT[(size_t)e*LL];
        #pragma unroll
        for (int u = 0; u < 20; ++u) {
            float2 qv = shq[u][e];
            accR[u] = fmaf(qv.x, kv.x, accR[u]); accR[u] = fmaf(-qv.y, kv.y, accR[u]);
            accI[u] = fmaf(qv.x, kv.y, accI[u]); accI[u] = fmaf( qv.y, kv.x, accI[u]);
        }
    }
    {   // e = 32: k imag is exactly 0
        float k32 = kT[(size_t)32*LL].x;
        #pragma unroll
        for (int u = 0; u < 20; ++u) {
            float2 qv = shq[u][32];
            accR[u] = fmaf(qv.x, k32, accR[u]);
            accI[u] = fmaf(qv.y, k32, accI[u]);
        }
    }
    const float sc = 0.125f;
    #pragma unroll
    for (int u = 0; u < 20; ++u)
        g_big[((size_t)bh*UU + ug*20 + u)*LL + j] = make_float2(accR[u]*sc, accI[u]*sc);
}

// ---------------- K6: fused softmax + upd (8 u per block) ----------------
#define SMU_SMEM (131072 + 33792 + 256)
__global__ void __launch_bounds__(512, 1) k_smupd()
{
    extern __shared__ char smc[];
    float2* p    = (float2*)smc;                       // [8][2048]
    float2* accs = (float2*)(smc + 131072);            // [16][8][33]
    float2* mxs  = (float2*)(smc + 131072 + 33792);    // [16]
    int bh = blockIdx.y, ug = blockIdx.x;
    int tid = threadIdx.x, warp = tid >> 5, lane = tid & 31;

    const float2* gb = g_big + ((size_t)bh*UU + ug*8)*LL;
    for (int i = tid; i < 8*LL; i += 512)
        p[i] = gb[i];
    __syncthreads();

    // softmax: warp w -> row u = w>>1, half = w&1
    int su = warp >> 1, half = warp & 1;
    float2* row = p + (su << 11) + (half << 10);
    float mr = -3.4e38f, mi = -3.4e38f;
    #pragma unroll 8
    for (int k2 = 0; k2 < 32; ++k2) {
        float2 vv = row[lane + k2*32];
        mr = fmaxf(mr, vv.x); mi = fmaxf(mi, vv.y);
    }
    #pragma unroll
    for (int o = 16; o; o >>= 1) {
        mr = fmaxf(mr, __shfl_xor_sync(0xffffffffu, mr, o));
        mi = fmaxf(mi, __shfl_xor_sync(0xffffffffu, mi, o));
    }
    if (lane == 0) mxs[warp] = make_float2(mr, mi);
    __syncthreads();
    {
        float2 a = mxs[su*2], b = mxs[su*2+1];
        mr = fmaxf(a.x, b.x); mi = fmaxf(a.y, b.y);
    }
    __syncthreads();
    float sr = 0.f, si = 0.f;
    #pragma unroll 8
    for (int k2 = 0; k2 < 32; ++k2) {
        float2 vv = row[lane + k2*32];
        float er = __expf(vv.x - mr);
        float ei = __expf(vv.y - mi);
        row[lane + k2*32] = make_float2(er, ei);
        sr += er; si += ei;
    }
    #pragma unroll
    for (int o = 16; o; o >>= 1) {
        sr += __shfl_xor_sync(0xffffffffu, sr, o);
        si += __shfl_xor_sync(0xffffffffu, si, o);
    }
    if (lane == 0) mxs[warp] = make_float2(sr, si);
    __syncthreads();
    {
        float2 a = mxs[su*2], b = mxs[su*2+1];
        float inr = 1.0f / (a.x + b.x);
        float ini = 1.0f / (a.y + b.y);
        #pragma unroll 8
        for (int k2 = 0; k2 < 32; ++k2) {
            float2 vv = row[lane + k2*32];
            row[lane + k2*32] = make_float2(vv.x * inr, vv.y * ini);
        }
    }
    __syncthreads();

    // upd main: lane = e (0..31 only), warp-strided over l
    float aR[8], aI[8];
    #pragma unroll
    for (int u = 0; u < 8; ++u) { aR[u]=0.f; aI[u]=0.f; }
    const float2* vb = g_vf + (size_t)bh*LL*EE;
    for (int l = warp; l < LL; l += 16) {
        float2 v2 = vb[(size_t)l*EE + lane];
        #pragma unroll
        for (int u = 0; u < 8; ++u) {
            float2 pp = p[(u << 11) + l];
            aR[u] = fmaf(pp.x, v2.x, aR[u]);
            aI[u] = fmaf(pp.y, v2.y, aI[u]);
        }
    }
    // e = 32 channel: v.im[32] == 0, so upd[u][32] = (sum attn_r*v32r, 0)
    float s32[8];
    #pragma unroll
    for (int u = 0; u < 8; ++u) s32[u] = 0.f;
    for (int l = tid; l < LL; l += 512) {
        float v32r = vb[(size_t)l*EE + 32].x;
        #pragma unroll
        for (int u = 0; u < 8; ++u)
            s32[u] = fmaf(p[(u << 11) + l].x, v32r, s32[u]);
    }
    #pragma unroll
    for (int o = 16; o; o >>= 1) {
        #pragma unroll
        for (int u = 0; u < 8; ++u)
            s32[u] += __shfl_xor_sync(0xffffffffu, s32[u], o);
    }
    #pragma unroll
    for (int u = 0; u < 8; ++u) {
        accs[(warp*8 + u)*EE + lane] = make_float2(aR[u], aI[u]);
        if (lane == 0) accs[(warp*8 + u)*EE + 32] = make_float2(s32[u], 0.f);
    }
    __syncthreads();
    for (int t = tid; t < 8*EE; t += 512) {
        int u = t / EE, e = t - u*EE;
        float ssr = 0.f, ssi = 0.f;
        #pragma unroll
        for (int w = 0; w < 16; ++w) {
            float2 a = accs[(w*8 + u)*EE + e];
            ssr += a.x; ssi += a.y;
        }
        g_upd[((size_t)bh*UU + ug*8 + u)*EE + e] = make_float2(ssr, ssi);
    }
}

// ---------------- K7: scatter + irfft of selected rows ----------------
__global__ void k_out(float* __restrict__ out)
{
    __shared__ float tc[64], ts[64];
    __shared__ float2 ub[8][EE];
    int tid = threadIdx.x;
    if (tid < 64) {
        float s, c;
        sincospif(tid * (1.0f/32.0f), &s, &c);
        tc[tid] = c; ts[tid] = s;
    }
    __syncthreads();
    int warp = tid >> 5, lane = tid & 31;
    int r = blockIdx.x * 8 + warp;
    int bh = r >> 11;
    int slot = g_slot[r];
    float* op = out + (size_t)r * DD;
    if (slot < 0) {
        op[lane]      = g_vmt[bh*DD + lane];
        op[lane + 32] = g_vmt[bh*DD + lane + 32];
    } else {
        const float2* X = g_upd + ((size_t)bh*UU + slot)*EE;
        ub[warp][lane] = X[lane];
        if (lane == 0) ub[warp][32] = X[32];
        __syncwarp();
        float a0 = ub[warp][0].x;
        float a32 = ub[warp][32].x;
        float sgn = (lane & 1) ? -a32 : a32;
        float acc1 = a0 + sgn, acc2 = a0 + sgn;
        #pragma unroll
        for (int e = 1; e < 32; ++e) {
            float2 Xe = ub[warp][e];
            int j1 = (e * lane) & 63;
            int j2 = (e * (lane + 32)) & 63;
            acc1 += 2.f * (Xe.x*tc[j1] - Xe.y*ts[j1]);
            acc2 += 2.f * (Xe.x*tc[j2] - Xe.y*ts[j2]);
        }
        op[lane]      = acc1 * (1.0f/64.0f);
        op[lane + 32] = acc2 * (1.0f/64.0f);
    }
}

// ---------------- launch ----------------
extern "C" void kernel_launch(void* const* d_in, const int* in_sizes, int n_in,
                              void* d_out, int out_size)
{
    (void)in_sizes; (void)n_in; (void)out_size;
    const float* q = (const float*)d_in[0];
    const float* k = (const float*)d_in[1];
    const float* v = (const float*)d_in[2];
    const int* isamp = (const int*)d_in[4];
    float* out = (float*)d_out;

    cudaFuncSetAttribute(k_msample, cudaFuncAttributeMaxDynamicSharedMemorySize, MS_SMEM);
    cudaFuncSetAttribute(k_smupd,   cudaFuncAttributeMaxDynamicSharedMemorySize, SMU_SMEM);

    k_rfft     <<<dim3(ROWS/8, 3), 256>>>(q, k, v);
    k_transpose<<<dim3(LL/32, BHN), 256>>>();
    k_vmt      <<<BHN, 512>>>(v);
    k_msample  <<<dim3(LL/256, BHN), 1024, MS_SMEM>>>(isamp);
    k_topk     <<<BHN, 256>>>();
    k_scores   <<<dim3(4, 2, BHN), 512>>>();
    k_smupd    <<<dim3(5, BHN), 512, SMU_SMEM>>>();
    k_out      <<<ROWS/8, 256>>>(out);
}

// round 10
// speedup vs baseline: 1.2802x; 1.1218x over previous
#include <cuda_runtime.h>
#include <cstdint>
#include <cstddef>

#define BB 8
#define LL 2048
#define HH 8
#define DD 64
#define EE 33
#define UU 40
#define SK 40
#define BHN (BB*HH)
#define ROWS (BHN*LL)

// ---------------- static scratch ----------------
__device__ float2 g_qf [ROWS*EE];
__device__ float2 g_kf [ROWS*EE];
__device__ float2 g_vf [ROWS*EE];
__device__ float2 g_kfT[ROWS*EE];
__device__ float4 g_kfC[(size_t)BHN*8*4096];
__device__ float  g_k32[BHN*LL];
__device__ float  g_M  [ROWS];
__device__ int    g_top [BHN*UU];
__device__ int    g_slot[ROWS];
__device__ float2 g_upd [BHN*UU*EE];
__device__ float  g_vmt[BHN*DD];
__device__ float2 g_big [(size_t)BHN*UU*LL];

__device__ __forceinline__ void cpa16(void* s, const void* g) {
    unsigned sa = (unsigned)__cvta_generic_to_shared(s);
    asm volatile("cp.async.cg.shared.global [%0], [%1], 16;" :: "r"(sa), "l"(g));
}
__device__ __forceinline__ void cp_commit() {
    asm volatile("cp.async.commit_group;" ::: "memory");
}
__device__ __forceinline__ void cp_wait1() {
    asm volatile("cp.async.wait_group 1;" ::: "memory");
}
__device__ __forceinline__ void cp_wait0() {
    asm volatile("cp.async.wait_group 0;" ::: "memory");
}

// ---------------- K1: rfft, 4 rows per warp ----------------
__global__ void k_rfft(const float* __restrict__ q,
                       const float* __restrict__ k,
                       const float* __restrict__ v)
{
    __shared__ float2 w32t[16], w64t[32];
    __shared__ float2 zs[8][32];
    int tid = threadIdx.x;
    if (tid < 16) {
        float s, c;
        sincospif(tid * (1.0f/16.0f), &s, &c);
        w32t[tid] = make_float2(c, s);
    } else if (tid < 48) {
        float s, c;
        sincospif((tid - 16) * (1.0f/32.0f), &s, &c);
        w64t[tid - 16] = make_float2(c, s);
    }
    __syncthreads();
    int warp = tid >> 5, lane = tid & 31;
    const float* src = (blockIdx.y == 0) ? q : (blockIdx.y == 1) ? k : v;
    float2* out = (blockIdx.y == 0) ? g_qf : (blockIdx.y == 1) ? g_kf : g_vf;
    #pragma unroll 1
    for (int i = 0; i < 4; ++i) {
        int r  = blockIdx.x * 32 + warp * 4 + i;
        int l  = r & (LL - 1);
        int bh = r >> 11;
        int b = bh >> 3, h = bh & 7;
        const float2* x2 = (const float2*)(src + (((size_t)b*LL + l)*HH + h) * DD);
        float2 z = x2[lane];
        float zr = z.x, zi = z.y;
        #pragma unroll
        for (int s = 0; s < 5; ++s) {
            int hm = 16 >> s;
            float orr = __shfl_xor_sync(0xffffffffu, zr, hm);
            float oii = __shfl_xor_sync(0xffffffffu, zi, hm);
            float2 w = w32t[(lane & (hm - 1)) << s];
            float dx = orr - zr, dy = oii - zi;
            float hr = dx*w.x + dy*w.y;
            float hi = dy*w.x - dx*w.y;
            float lr = zr + orr, li = zi + oii;
            bool top = (lane & hm) != 0;
            zr = top ? hr : lr;
            zi = top ? hi : li;
        }
        int bin = __brev((unsigned)lane) >> 27;
        zs[warp][bin] = make_float2(zr, zi);
        __syncwarp();
        float2 m = zs[warp][(32 - bin) & 31];
        __syncwarp();
        float Zer = 0.5f*(zr + m.x), Zei = 0.5f*(zi - m.y);
        float Zor = 0.5f*(zi + m.y), Zoi = -0.5f*(zr - m.x);
        float2 w = w64t[bin];
        float Xr = Zer + w.x*Zor + w.y*Zoi;
        float Xi = Zei + w.x*Zoi - w.y*Zor;
        out[(size_t)r*EE + bin] = make_float2(Xr, Xi);
        if (bin == 0) out[(size_t)r*EE + 32] = make_float2(zr - zi, 0.f);
    }
}

// ---------------- K2: transpose k_fft -> e-major + chunked row-major ----------------
__global__ void k_transpose()
{
    __shared__ float2 tile[32][EE];
    int bh = blockIdx.y;
    int l0 = blockIdx.x * 32;
    for (int t = threadIdx.x; t < 32*EE; t += 256) {
        int r = t / EE, e = t - r*EE;
        tile[r][e] = g_kf[((size_t)bh*LL + l0 + r)*EE + e];
    }
    __syncthreads();
    for (int t = threadIdx.x; t < EE*32; t += 256) {
        int e = t >> 5, r = t & 31;
        g_kfT[((size_t)bh*EE + e)*LL + l0 + r] = tile[r][e];
    }
    for (int t = threadIdx.x; t < 512; t += 256) {
        int half = t >> 8;
        int c    = (t >> 5) & 7;
        int r    = t & 31;
        float2 a = tile[r][c*4 + half*2];
        float2 b = tile[r][c*4 + half*2 + 1];
        g_kfC[(((size_t)(bh*8 + c)) << 12) + (size_t)(l0 + r)*2 + half] =
            make_float4(a.x, a.y, b.x, b.y);
    }
    if (threadIdx.x < 32)
        g_k32[bh*LL + l0 + threadIdx.x] = tile[threadIdx.x][32].x;
}

// ---------------- K2b: time-domain v mean ----------------
__global__ void k_vmt(const float* __restrict__ v)
{
    __shared__ float part[8][64];
    int bh = blockIdx.x, b = bh >> 3, h = bh & 7;
    int tid = threadIdx.x;
    int d = tid & 63, g = tid >> 6;
    const float* base = v + (((size_t)b*LL)*HH + h) * DD + d;
    float acc = 0.f;
    #pragma unroll 8
    for (int i = g; i < LL; i += 8) acc += base[(size_t)i * (HH*DD)];
    part[g][d] = acc;
    __syncthreads();
    if (tid < 64) {
        float s = 0.f;
        #pragma unroll
        for (int g2 = 0; g2 < 8; ++g2) s += part[g2][tid];
        g_vmt[bh*DD + tid] = s * (1.0f/LL);
    }
}

// ---------------- K3: sampled QK -> M ----------------
#define MS_SMEM (131072 + 8192 + 16384)
__global__ void __launch_bounds__(1024, 1) k_msample(const int* __restrict__ isamp)
{
    extern __shared__ char sm[];
    float4* kbuf = (float4*)sm;
    float*  sk32 = (float*)(sm + 131072);
    float4* pt   = (float4*)(sm + 131072 + 8192);

    int tid = threadIdx.x;
    int l0  = blockIdx.x * 256;
    int bh  = blockIdx.y;
    int sg  = tid & 3;
    int lq  = tid >> 2;
    int l   = l0 + lq;

    sk32[tid]        = g_k32[bh*LL + tid];
    sk32[tid + 1024] = g_k32[bh*LL + tid + 1024];

    const int* ip = isamp + l*SK + sg*10;
    int ids[10];
    #pragma unroll
    for (int i = 0; i < 10; ++i) ids[i] = ip[i];

    const float4* kc = g_kfC + (((size_t)(bh*8)) << 12);
    #pragma unroll
    for (int it = 0; it < 4; ++it) {
        int lin = it*1024 + tid;
        int sw  = lin ^ ((lin >> 3) & 7);
        cpa16(&kbuf[sw], &kc[lin]);
    }
    cp_commit();

    float accR[10], accI[10];
    #pragma unroll
    for (int s = 0; s < 10; ++s) { accR[s] = 0.f; accI[s] = 0.f; }
    const float2* qrow = g_qf + (size_t)(bh*LL + l)*EE;

    #pragma unroll 1
    for (int c = 0; c < 8; ++c) {
        int cur = (c & 1) << 12;
        if (c < 7) {
            const float4* src = kc + ((size_t)(c+1) << 12);
            int nb = ((c+1) & 1) << 12;
            #pragma unroll
            for (int it = 0; it < 4; ++it) {
                int lin = it*1024 + tid;
                int sw  = lin ^ ((lin >> 3) & 7);
                cpa16(&kbuf[nb + sw], &src[lin]);
            }
            cp_commit();
            cp_wait1();
        } else {
            cp_wait0();
        }
        __syncthreads();
        float2 q0 = qrow[4*c], q1 = qrow[4*c+1], q2 = qrow[4*c+2], q3 = qrow[4*c+3];
        #pragma unroll
        for (int s = 0; s < 10; ++s) {
            int id = ids[s];
            int p = id << 1, x = (id >> 2) & 7;
            float4 h0 = kbuf[cur + (p ^ x)];
            float4 h1 = kbuf[cur + ((p + 1) ^ x)];
            accR[s] = fmaf(q0.x, h0.x, accR[s]); accR[s] = fmaf(-q0.y, h0.y, accR[s]);
            accI[s] = fmaf(q0.x, h0.y, accI[s]); accI[s] = fmaf( q0.y, h0.x, accI[s]);
            accR[s] = fmaf(q1.x, h0.z, accR[s]); accR[s] = fmaf(-q1.y, h0.w, accR[s]);
            accI[s] = fmaf(q1.x, h0.w, accI[s]); accI[s] = fmaf( q1.y, h0.z, accI[s]);
            accR[s] = fmaf(q2.x, h1.x, accR[s]); accR[s] = fmaf(-q2.y, h1.y, accR[s]);
            accI[s] = fmaf(q2.x, h1.y, accI[s]); accI[s] = fmaf( q2.y, h1.x, accI[s]);
            accR[s] = fmaf(q3.x, h1.z, accR[s]); accR[s] = fmaf(-q3.y, h1.w, accR[s]);
            accI[s] = fmaf(q3.x, h1.w, accI[s]); accI[s] = fmaf( q3.y, h1.z, accI[s]);
        }
        __syncthreads();
    }
    {
        float q32 = qrow[32].x;
        #pragma unroll
        for (int s = 0; s < 10; ++s)
            accR[s] = fmaf(q32, sk32[ids[s]], accR[s]);
    }
    float mr = -3.4e38f, mi = -3.4e38f, sr = 0.f, si = 0.f;
    #pragma unroll
    for (int s = 0; s < 10; ++s) {
        mr = fmaxf(mr, accR[s]); mi = fmaxf(mi, accI[s]);
        sr += accR[s];           si += accI[s];
    }
    pt[sg*256 + lq] = make_float4(mr, mi, sr, si);
    __syncthreads();
    if (tid < 256) {
        float4 a = pt[tid], b = pt[256 + tid], c2 = pt[512 + tid], d = pt[768 + tid];
        float MR = fmaxf(fmaxf(a.x, b.x), fmaxf(c2.x, d.x));
        float MI = fmaxf(fmaxf(a.y, b.y), fmaxf(c2.y, d.y));
        float SR = a.z + b.z + c2.z + d.z;
        float SI = a.w + b.w + c2.w + d.w;
        g_M[(size_t)bh*LL + l0 + tid] = MR + MI - (SR + SI) * (1.0f/LL);
    }
}

// ---------------- K4: top-40 per bh ----------------
__global__ void k_topk()
{
    __shared__ float mv[LL];
    __shared__ float wv[8];
    __shared__ int   wi[8];
    int bh = blockIdx.x, tid = threadIdx.x, lane = tid & 31, warp = tid >> 5;
    for (int i = tid; i < LL; i += 256) {
        mv[i] = g_M[bh*LL + i];
        g_slot[bh*LL + i] = -1;
    }
    __syncthreads();
    for (int u = 0; u < UU; ++u) {
        float best = -3.4e38f; int bi = 1 << 30;
        for (int i = tid; i < LL; i += 256) {
            float x = mv[i];
            if (x > best) { best = x; bi = i; }
        }
        #pragma unroll
        for (int o = 16; o; o >>= 1) {
            float ov = __shfl_xor_sync(0xffffffffu, best, o);
            int   oi = __shfl_xor_sync(0xffffffffu, bi, o);
            if (ov > best || (ov == best && oi < bi)) { best = ov; bi = oi; }
        }
        if (lane == 0) { wv[warp] = best; wi[warp] = bi; }
        __syncthreads();
        if (warp == 0) {
            float b2 = (lane < 8) ? wv[lane] : -3.4e38f;
            int   i2 = (lane < 8) ? wi[lane] : (1 << 30);
            #pragma unroll
            for (int o = 4; o; o >>= 1) {
                float ov = __shfl_xor_sync(0xffffffffu, b2, o);
                int   oi = __shfl_xor_sync(0xffffffffu, i2, o);
                if (ov > b2 || (ov == b2 && oi < i2)) { b2 = ov; i2 = oi; }
            }
            if (lane == 0) {
                g_top[bh*UU + u] = i2;
                g_slot[bh*LL + i2] = u;
                mv[i2] = -3.4e38f;
            }
        }
        __syncthreads();
    }
}

// ---------------- K5: full scores, 10-u register blocked ----------------
__global__ void __launch_bounds__(512) k_scores()
{
    __shared__ float2 shq[10][EE];
    int bh = blockIdx.z;
    int ug = blockIdx.y;     // 0..3
    int jt = blockIdx.x;     // 0..3
    int tid = threadIdx.x;
    for (int t = tid; t < 10*EE; t += 512) {
        int ul = t / EE, e = t - ul*EE;
        int qi = g_top[bh*UU + ug*10 + ul];
        shq[ul][e] = g_qf[((size_t)bh*LL + qi)*EE + e];
    }
    __syncthreads();
    int j = jt*512 + tid;
    float accR[10], accI[10];
    #pragma unroll
    for (int u = 0; u < 10; ++u) { accR[u] = 0.f; accI[u] = 0.f; }
    const float2* kT = g_kfT + (size_t)bh*EE*LL + j;
    for (int e = 0; e < 32; ++e) {
        float2 kv = kT[(size_t)e*LL];
        #pragma unroll
        for (int u = 0; u < 10; ++u) {
            float2 qv = shq[u][e];
            accR[u] = fmaf(qv.x, kv.x, accR[u]); accR[u] = fmaf(-qv.y, kv.y, accR[u]);
            accI[u] = fmaf(qv.x, kv.y, accI[u]); accI[u] = fmaf( qv.y, kv.x, accI[u]);
        }
    }
    {   // e = 32: k imag is exactly 0
        float k32 = kT[(size_t)32*LL].x;
        #pragma unroll
        for (int u = 0; u < 10; ++u) {
            float2 qv = shq[u][32];
            accR[u] = fmaf(qv.x, k32, accR[u]);
            accI[u] = fmaf(qv.y, k32, accI[u]);
        }
    }
    const float sc = 0.125f;
    #pragma unroll
    for (int u = 0; u < 10; ++u)
        g_big[((size_t)bh*UU + ug*10 + u)*LL + j] = make_float2(accR[u]*sc, accI[u]*sc);
}

// ---------------- K6: fused softmax + upd (4 u per block, 2 blocks/SM) ----------------
#define SMU_SMEM (65536 + 16896 + 128)
__global__ void __launch_bounds__(512) k_smupd()
{
    extern __shared__ char smc[];
    float2* p    = (float2*)smc;                       // [4][2048]
    float2* accs = (float2*)(smc + 65536);             // [16][4][33]
    float2* mxs  = (float2*)(smc + 65536 + 16896);     // [16]
    int bh = blockIdx.y, ug = blockIdx.x;              // ug 0..9
    int tid = threadIdx.x, warp = tid >> 5, lane = tid & 31;

    const float2* gb = g_big + ((size_t)bh*UU + ug*4)*LL;
    for (int i = tid; i < 4*LL; i += 512)
        p[i] = gb[i];
    __syncthreads();

    // softmax: warp w -> row u = w>>2, quarter = w&3 (512 elems each)
    int su = warp >> 2, qt = warp & 3;
    float2* row = p + (su << 11) + (qt << 9);
    float mr = -3.4e38f, mi = -3.4e38f;
    #pragma unroll 8
    for (int k2 = 0; k2 < 16; ++k2) {
        float2 vv = row[lane + k2*32];
        mr = fmaxf(mr, vv.x); mi = fmaxf(mi, vv.y);
    }
    #pragma unroll
    for (int o = 16; o; o >>= 1) {
        mr = fmaxf(mr, __shfl_xor_sync(0xffffffffu, mr, o));
        mi = fmaxf(mi, __shfl_xor_sync(0xffffffffu, mi, o));
    }
    if (lane == 0) mxs[warp] = make_float2(mr, mi);
    __syncthreads();
    {
        float2 a = mxs[su*4], b = mxs[su*4+1], c = mxs[su*4+2], d = mxs[su*4+3];
        mr = fmaxf(fmaxf(a.x, b.x), fmaxf(c.x, d.x));
        mi = fmaxf(fmaxf(a.y, b.y), fmaxf(c.y, d.y));
    }
    __syncthreads();
    float sr = 0.f, si = 0.f;
    #pragma unroll 8
    for (int k2 = 0; k2 < 16; ++k2) {
        float2 vv = row[lane + k2*32];
        float er = __expf(vv.x - mr);
        float ei = __expf(vv.y - mi);
        row[lane + k2*32] = make_float2(er, ei);
        sr += er; si += ei;
    }
    #pragma unroll
    for (int o = 16; o; o >>= 1) {
        sr += __shfl_xor_sync(0xffffffffu, sr, o);
        si += __shfl_xor_sync(0xffffffffu, si, o);
    }
    if (lane == 0) mxs[warp] = make_float2(sr, si);
    __syncthreads();
    {
        float2 a = mxs[su*4], b = mxs[su*4+1], c = mxs[su*4+2], d = mxs[su*4+3];
        float inr = 1.0f / (a.x + b.x + c.x + d.x);
        float ini = 1.0f / (a.y + b.y + c.y + d.y);
        #pragma unroll 8
        for (int k2 = 0; k2 < 16; ++k2) {
            float2 vv = row[lane + k2*32];
            row[lane + k2*32] = make_float2(vv.x * inr, vv.y * ini);
        }
    }
    __syncthreads();

    // upd main: lane = e (0..31), warp-strided over l
    float aR[4], aI[4];
    #pragma unroll
    for (int u = 0; u < 4; ++u) { aR[u]=0.f; aI[u]=0.f; }
    const float2* vb = g_vf + (size_t)bh*LL*EE;
    for (int l = warp; l < LL; l += 16) {
        float2 v2 = vb[(size_t)l*EE + lane];
        #pragma unroll
        for (int u = 0; u < 4; ++u) {
            float2 pp = p[(u << 11) + l];
            aR[u] = fmaf(pp.x, v2.x, aR[u]);
            aI[u] = fmaf(pp.y, v2.y, aI[u]);
        }
    }
    // e = 32 channel: v.im[32] == 0
    float s32[4];
    #pragma unroll
    for (int u = 0; u < 4; ++u) s32[u] = 0.f;
    for (int l = tid; l < LL; l += 512) {
        float v32r = vb[(size_t)l*EE + 32].x;
        #pragma unroll
        for (int u = 0; u < 4; ++u)
            s32[u] = fmaf(p[(u << 11) + l].x, v32r, s32[u]);
    }
    #pragma unroll
    for (int o = 16; o; o >>= 1) {
        #pragma unroll
        for (int u = 0; u < 4; ++u)
            s32[u] += __shfl_xor_sync(0xffffffffu, s32[u], o);
    }
    #pragma unroll
    for (int u = 0; u < 4; ++u) {
        accs[(warp*4 + u)*EE + lane] = make_float2(aR[u], aI[u]);
        if (lane == 0) accs[(warp*4 + u)*EE + 32] = make_float2(s32[u], 0.f);
    }
    __syncthreads();
    for (int t = tid; t < 4*EE; t += 512) {
        int u = t / EE, e = t - u*EE;
        float ssr = 0.f, ssi = 0.f;
        #pragma unroll
        for (int w = 0; w < 16; ++w) {
            float2 a = accs[(w*4 + u)*EE + e];
            ssr += a.x; ssi += a.y;
        }
        g_upd[((size_t)bh*UU + ug*4 + u)*EE + e] = make_float2(ssr, ssi);
    }
}

// ---------------- K7: scatter + irfft, 4 rows per warp ----------------
__global__ void k_out(float* __restrict__ out)
{
    __shared__ float tc[64], ts[64];
    __shared__ float2 ub[8][EE];
    int tid = threadIdx.x;
    if (tid < 64) {
        float s, c;
        sincospif(tid * (1.0f/32.0f), &s, &c);
        tc[tid] = c; ts[tid] = s;
    }
    __syncthreads();
    int warp = tid >> 5, lane = tid & 31;
    #pragma unroll 1
    for (int i = 0; i < 4; ++i) {
        int r = blockIdx.x * 32 + warp * 4 + i;
        int bh = r >> 11;
        int slot = g_slot[r];
        float* op = out + (size_t)r * DD;
        if (slot < 0) {
            op[lane]      = g_vmt[bh*DD + lane];
            op[lane + 32] = g_vmt[bh*DD + lane + 32];
        } else {
            const float2* X = g_upd + ((size_t)bh*UU + slot)*EE;
            ub[warp][lane] = X[lane];
            if (lane == 0) ub[warp][32] = X[32];
            __syncwarp();
            float a0 = ub[warp][0].x;
            float a32 = ub[warp][32].x;
            float sgn = (lane & 1) ? -a32 : a32;
            float acc1 = a0 + sgn, acc2 = a0 + sgn;
            #pragma unroll
            for (int e = 1; e < 32; ++e) {
                float2 Xe = ub[warp][e];
                int j1 = (e * lane) & 63;
                int j2 = (e * (lane + 32)) & 63;
                acc1 += 2.f * (Xe.x*tc[j1] - Xe.y*ts[j1]);
                acc2 += 2.f * (Xe.x*tc[j2] - Xe.y*ts[j2]);
            }
            op[lane]      = acc1 * (1.0f/64.0f);
            op[lane + 32] = acc2 * (1.0f/64.0f);
            __syncwarp();
        }
    }
}

// ---------------- launch ----------------
extern "C" void kernel_launch(void* const* d_in, const int* in_sizes, int n_in,
                              void* d_out, int out_size)
{
    (void)in_sizes; (void)n_in; (void)out_size;
    const float* q = (const float*)d_in[0];
    const float* k = (const float*)d_in[1];
    const float* v = (const float*)d_in[2];
    const int* isamp = (const int*)d_in[4];
    float* out = (float*)d_out;

    cudaFuncSetAttribute(k_msample, cudaFuncAttributeMaxDynamicSharedMemorySize, MS_SMEM);
    cudaFuncSetAttribute(k_smupd,   cudaFuncAttributeMaxDynamicSharedMemorySize, SMU_SMEM);

    k_rfft     <<<dim3(ROWS/32, 3), 256>>>(q, k, v);
    k_transpose<<<dim3(LL/32, BHN), 256>>>();
    k_vmt      <<<BHN, 512>>>(v);
    k_msample  <<<dim3(LL/256, BHN), 1024, MS_SMEM>>>(isamp);
    k_topk     <<<BHN, 256>>>();
    k_scores   <<<dim3(4, 4, BHN), 512>>>();
    k_smupd    <<<dim3(10, BHN), 512, SMU_SMEM>>>();
    k_out      <<<ROWS/32, 256>>>(out);
}

// round 11
// speedup vs baseline: 1.3490x; 1.0538x over previous
#include <cuda_runtime.h>
#include <cstdint>
#include <cstddef>

#define BB 8
#define LL 2048
#define HH 8
#define DD 64
#define EE 33
#define UU 40
#define SK 40
#define BHN (BB*HH)
#define ROWS (BHN*LL)

// ---------------- static scratch ----------------
__device__ float2 g_qf [ROWS*EE];
__device__ float2 g_vf [ROWS*EE];
__device__ float4 g_kfC[(size_t)BHN*8*4096];   // [bh][chunk(8)][id*2+half]
__device__ float  g_k32[BHN*LL];
__device__ float  g_M  [ROWS];
__device__ int    g_top [BHN*UU];
__device__ int    g_slot[ROWS];
__device__ float2 g_upd [BHN*UU*EE];
__device__ float  g_vmt[BHN*DD];
__device__ float2 g_big [(size_t)BHN*UU*LL];

__device__ __forceinline__ void cpa16(void* s, const void* g) {
    unsigned sa = (unsigned)__cvta_generic_to_shared(s);
    asm volatile("cp.async.cg.shared.global [%0], [%1], 16;" :: "r"(sa), "l"(g));
}
__device__ __forceinline__ void cp_commit() {
    asm volatile("cp.async.commit_group;" ::: "memory");
}
__device__ __forceinline__ void cp_wait1() {
    asm volatile("cp.async.wait_group 1;" ::: "memory");
}
__device__ __forceinline__ void cp_wait0() {
    asm volatile("cp.async.wait_group 0;" ::: "memory");
}

// ---------------- K1: rfft, 4 rows per warp; k-branch writes chunked layout ----------------
__global__ void k_rfft(const float* __restrict__ q,
                       const float* __restrict__ k,
                       const float* __restrict__ v)
{
    __shared__ float2 w32t[16], w64t[32];
    __shared__ float2 zs[8][32];
    int tid = threadIdx.x;
    if (tid < 16) {
        float s, c;
        sincospif(tid * (1.0f/16.0f), &s, &c);
        w32t[tid] = make_float2(c, s);
    } else if (tid < 48) {
        float s, c;
        sincospif((tid - 16) * (1.0f/32.0f), &s, &c);
        w64t[tid - 16] = make_float2(c, s);
    }
    __syncthreads();
    int warp = tid >> 5, lane = tid & 31;
    int which = blockIdx.y;
    const float* src = (which == 0) ? q : (which == 1) ? k : v;
    float2* out = (which == 0) ? g_qf : g_vf;
    #pragma unroll 1
    for (int i = 0; i < 4; ++i) {
        int r  = blockIdx.x * 32 + warp * 4 + i;
        int l  = r & (LL - 1);
        int bh = r >> 11;
        int b = bh >> 3, h = bh & 7;
        const float2* x2 = (const float2*)(src + (((size_t)b*LL + l)*HH + h) * DD);
        float2 z = x2[lane];
        float zr = z.x, zi = z.y;
        #pragma unroll
        for (int s = 0; s < 5; ++s) {
            int hm = 16 >> s;
            float orr = __shfl_xor_sync(0xffffffffu, zr, hm);
            float oii = __shfl_xor_sync(0xffffffffu, zi, hm);
            float2 w = w32t[(lane & (hm - 1)) << s];
            float dx = orr - zr, dy = oii - zi;
            float hr = dx*w.x + dy*w.y;
            float hi = dy*w.x - dx*w.y;
            float lr = zr + orr, li = zi + oii;
            bool top = (lane & hm) != 0;
            zr = top ? hr : lr;
            zi = top ? hi : li;
        }
        int bin = __brev((unsigned)lane) >> 27;
        zs[warp][bin] = make_float2(zr, zi);
        __syncwarp();
        float2 m = zs[warp][(32 - bin) & 31];
        __syncwarp();
        float Zer = 0.5f*(zr + m.x), Zei = 0.5f*(zi - m.y);
        float Zor = 0.5f*(zi + m.y), Zoi = -0.5f*(zr - m.x);
        float2 w = w64t[bin];
        float Xr = Zer + w.x*Zor + w.y*Zoi;
        float Xi = Zei + w.x*Zoi - w.y*Zor;
        if (which == 1) {
            // chunked key layout: chunk = bin>>2; float4 pair index half = (bin>>1)&1
            int c = bin >> 2, half = (bin >> 1) & 1;
            float2* kc2 = (float2*)g_kfC;
            size_t idx = ((((size_t)(bh*8 + c)) << 12) + (size_t)l*2 + half)*2 + (bin & 1);
            kc2[idx] = make_float2(Xr, Xi);
            if (bin == 0) g_k32[bh*LL + l] = zr - zi;   // bin-32 real value
        } else {
            out[(size_t)r*EE + bin] = make_float2(Xr, Xi);
            if (bin == 0) out[(size_t)r*EE + 32] = make_float2(zr - zi, 0.f);
        }
    }
}

// ---------------- K2b: time-domain v mean ----------------
__global__ void k_vmt(const float* __restrict__ v)
{
    __shared__ float part[8][64];
    int bh = blockIdx.x, b = bh >> 3, h = bh & 7;
    int tid = threadIdx.x;
    int d = tid & 63, g = tid >> 6;
    const float* base = v + (((size_t)b*LL)*HH + h) * DD + d;
    float acc = 0.f;
    #pragma unroll 8
    for (int i = g; i < LL; i += 8) acc += base[(size_t)i * (HH*DD)];
    part[g][d] = acc;
    __syncthreads();
    if (tid < 64) {
        float s = 0.f;
        #pragma unroll
        for (int g2 = 0; g2 < 8; ++g2) s += part[g2][tid];
        g_vmt[bh*DD + tid] = s * (1.0f/LL);
    }
}

// ---------------- K3: sampled QK -> M (smem keys + staged q) ----------------
#define MS_KBUF   131072
#define MS_SK32   (MS_KBUF)                 // offset after kbuf
#define MS_PT     (MS_KBUF + 8192)
#define MS_QS     (MS_KBUF + 8192 + 16384)
#define MS_SMEM   (MS_KBUF + 8192 + 16384 + 10240)
__global__ void __launch_bounds__(1024, 1) k_msample(const int* __restrict__ isamp)
{
    extern __shared__ char sm[];
    float4* kbuf = (float4*)sm;
    float*  sk32 = (float*)(sm + MS_SK32);
    float4* pt   = (float4*)(sm + MS_PT);
    float2* qs   = (float2*)(sm + MS_QS);    // [256][5] padded

    int tid = threadIdx.x;
    int l0  = blockIdx.x * 256;
    int bh  = blockIdx.y;
    int sg  = tid & 3;
    int lq  = tid >> 2;
    int l   = l0 + lq;

    sk32[tid]        = g_k32[bh*LL + tid];
    sk32[tid + 1024] = g_k32[bh*LL + tid + 1024];

    const int* ip = isamp + l*SK + sg*10;
    int ids[10];
    #pragma unroll
    for (int i = 0; i < 10; ++i) ids[i] = ip[i];

    float q32 = g_qf[((size_t)(bh*LL + l))*EE + 32].x;

    const float4* kc = g_kfC + (((size_t)(bh*8)) << 12);
    #pragma unroll
    for (int it = 0; it < 4; ++it) {
        int lin = it*1024 + tid;
        int sw  = lin ^ ((lin >> 3) & 7);
        cpa16(&kbuf[sw], &kc[lin]);
    }
    cp_commit();

    float accR[10], accI[10];
    #pragma unroll
    for (int s = 0; s < 10; ++s) { accR[s] = 0.f; accI[s] = 0.f; }

    int qrow_s = tid >> 2, qbin_s = tid & 3;     // for cooperative q staging
    const float2* qsrc = g_qf + (size_t)(bh*LL + l0 + qrow_s)*EE + qbin_s;

    #pragma unroll 1
    for (int c = 0; c < 8; ++c) {
        // stage q bins 4c..4c+3 for all 256 rows (prev compute done at loop-end sync)
        qs[qrow_s*5 + qbin_s] = qsrc[4*c];
        int cur = (c & 1) << 12;
        if (c < 7) {
            const float4* src = kc + ((size_t)(c+1) << 12);
            int nb = ((c+1) & 1) << 12;
            #pragma unroll
            for (int it = 0; it < 4; ++it) {
                int lin = it*1024 + tid;
                int sw  = lin ^ ((lin >> 3) & 7);
                cpa16(&kbuf[nb + sw], &src[lin]);
            }
            cp_commit();
            cp_wait1();
        } else {
            cp_wait0();
        }
        __syncthreads();
        float2 q0 = qs[lq*5 + 0], q1 = qs[lq*5 + 1], q2 = qs[lq*5 + 2], q3 = qs[lq*5 + 3];
        #pragma unroll
        for (int s = 0; s < 10; ++s) {
            int id = ids[s];
            int p = id << 1, x = (id >> 2) & 7;
            float4 h0 = kbuf[cur + (p ^ x)];
            float4 h1 = kbuf[cur + ((p + 1) ^ x)];
            accR[s] = fmaf(q0.x, h0.x, accR[s]); accR[s] = fmaf(-q0.y, h0.y, accR[s]);
            accI[s] = fmaf(q0.x, h0.y, accI[s]); accI[s] = fmaf( q0.y, h0.x, accI[s]);
            accR[s] = fmaf(q1.x, h0.z, accR[s]); accR[s] = fmaf(-q1.y, h0.w, accR[s]);
            accI[s] = fmaf(q1.x, h0.w, accI[s]); accI[s] = fmaf( q1.y, h0.z, accI[s]);
            accR[s] = fmaf(q2.x, h1.x, accR[s]); accR[s] = fmaf(-q2.y, h1.y, accR[s]);
            accI[s] = fmaf(q2.x, h1.y, accI[s]); accI[s] = fmaf( q2.y, h1.x, accI[s]);
            accR[s] = fmaf(q3.x, h1.z, accR[s]); accR[s] = fmaf(-q3.y, h1.w, accR[s]);
            accI[s] = fmaf(q3.x, h1.w, accI[s]); accI[s] = fmaf( q3.y, h1.z, accI[s]);
        }
        __syncthreads();
    }
    #pragma unroll
    for (int s = 0; s < 10; ++s)
        accR[s] = fmaf(q32, sk32[ids[s]], accR[s]);

    float mr = -3.4e38f, mi = -3.4e38f, sr = 0.f, si = 0.f;
    #pragma unroll
    for (int s = 0; s < 10; ++s) {
        mr = fmaxf(mr, accR[s]); mi = fmaxf(mi, accI[s]);
        sr += accR[s];           si += accI[s];
    }
    pt[sg*256 + lq] = make_float4(mr, mi, sr, si);
    __syncthreads();
    if (tid < 256) {
        float4 a = pt[tid], b = pt[256 + tid], c2 = pt[512 + tid], d = pt[768 + tid];
        float MR = fmaxf(fmaxf(a.x, b.x), fmaxf(c2.x, d.x));
        float MI = fmaxf(fmaxf(a.y, b.y), fmaxf(c2.y, d.y));
        float SR = a.z + b.z + c2.z + d.z;
        float SI = a.w + b.w + c2.w + d.w;
        g_M[(size_t)bh*LL + l0 + tid] = MR + MI - (SR + SI) * (1.0f/LL);
    }
}

// ---------------- K4: top-40 per bh ----------------
__global__ void k_topk()
{
    __shared__ float mv[LL];
    __shared__ float wv[8];
    __shared__ int   wi[8];
    int bh = blockIdx.x, tid = threadIdx.x, lane = tid & 31, warp = tid >> 5;
    for (int i = tid; i < LL; i += 256) {
        mv[i] = g_M[bh*LL + i];
        g_slot[bh*LL + i] = -1;
    }
    __syncthreads();
    for (int u = 0; u < UU; ++u) {
        float best = -3.4e38f; int bi = 1 << 30;
        for (int i = tid; i < LL; i += 256) {
            float x = mv[i];
            if (x > best) { best = x; bi = i; }
        }
        #pragma unroll
        for (int o = 16; o; o >>= 1) {
            float ov = __shfl_xor_sync(0xffffffffu, best, o);
            int   oi = __shfl_xor_sync(0xffffffffu, bi, o);
            if (ov > best || (ov == best && oi < bi)) { best = ov; bi = oi; }
        }
        if (lane == 0) { wv[warp] = best; wi[warp] = bi; }
        __syncthreads();
        if (warp == 0) {
            float b2 = (lane < 8) ? wv[lane] : -3.4e38f;
            int   i2 = (lane < 8) ? wi[lane] : (1 << 30);
            #pragma unroll
            for (int o = 4; o; o >>= 1) {
                float ov = __shfl_xor_sync(0xffffffffu, b2, o);
                int   oi = __shfl_xor_sync(0xffffffffu, i2, o);
                if (ov > b2 || (ov == b2 && oi < i2)) { b2 = ov; i2 = oi; }
            }
            if (lane == 0) {
                g_top[bh*UU + u] = i2;
                g_slot[bh*LL + i2] = u;
                mv[i2] = -3.4e38f;
            }
        }
        __syncthreads();
    }
}

// ---------------- K5: full scores from chunked keys, 10-u register blocked ----------------
__global__ void __launch_bounds__(512) k_scores()
{
    __shared__ float2 shq[10][EE];
    int bh = blockIdx.z;
    int ug = blockIdx.y;     // 0..3
    int jt = blockIdx.x;     // 0..3
    int tid = threadIdx.x;
    for (int t = tid; t < 10*EE; t += 512) {
        int ul = t / EE, e = t - ul*EE;
        int qi = g_top[bh*UU + ug*10 + ul];
        shq[ul][e] = g_qf[((size_t)bh*LL + qi)*EE + e];
    }
    __syncthreads();
    int j = jt*512 + tid;
    float accR[10], accI[10];
    #pragma unroll
    for (int u = 0; u < 10; ++u) { accR[u] = 0.f; accI[u] = 0.f; }
    const float4* kc = g_kfC + (((size_t)(bh*8)) << 12);
    #pragma unroll 1
    for (int c = 0; c < 8; ++c) {
        float4 h0 = kc[((size_t)c << 12) + j*2];
        float4 h1 = kc[((size_t)c << 12) + j*2 + 1];
        #pragma unroll
        for (int u = 0; u < 10; ++u) {
            float2 q0 = shq[u][4*c], q1 = shq[u][4*c+1], q2 = shq[u][4*c+2], q3 = shq[u][4*c+3];
            accR[u] = fmaf(q0.x, h0.x, accR[u]); accR[u] = fmaf(-q0.y, h0.y, accR[u]);
            accI[u] = fmaf(q0.x, h0.y, accI[u]); accI[u] = fmaf( q0.y, h0.x, accI[u]);
            accR[u] = fmaf(q1.x, h0.z, accR[u]); accR[u] = fmaf(-q1.y, h0.w, accR[u]);
            accI[u] = fmaf(q1.x, h0.w, accI[u]); accI[u] = fmaf( q1.y, h0.z, accI[u]);
            accR[u] = fmaf(q2.x, h1.x, accR[u]); accR[u] = fmaf(-q2.y, h1.y, accR[u]);
            accI[u] = fmaf(q2.x, h1.y, accI[u]); accI[u] = fmaf( q2.y, h1.x, accI[u]);
            accR[u] = fmaf(q3.x, h1.z, accR[u]); accR[u] = fmaf(-q3.y, h1.w, accR[u]);
            accI[u] = fmaf(q3.x, h1.w, accI[u]); accI[u] = fmaf( q3.y, h1.z, accI[u]);
        }
    }
    {   // e = 32: k imag exactly 0
        float k32 = g_k32[bh*LL + j];
        #pragma unroll
        for (int u = 0; u < 10; ++u) {
            float2 qv = shq[u][32];
            accR[u] = fmaf(qv.x, k32, accR[u]);
            accI[u] = fmaf(qv.y, k32, accI[u]);
        }
    }
    const float sc = 0.125f;
    #pragma unroll
    for (int u = 0; u < 10; ++u)
        g_big[((size_t)bh*UU + ug*10 + u)*LL + j] = make_float2(accR[u]*sc, accI[u]*sc);
}

// ---------------- K6: fused softmax + upd (4 u per block, 2 blocks/SM) ----------------
#define SMU_SMEM (65536 + 16896 + 128)
__global__ void __launch_bounds__(512) k_smupd()
{
    extern __shared__ char smc[];
    float2* p    = (float2*)smc;                       // [4][2048]
    float2* accs = (float2*)(smc + 65536);             // [16][4][33]
    float2* mxs  = (float2*)(smc + 65536 + 16896);     // [16]
    int bh = blockIdx.y, ug = blockIdx.x;              // ug 0..9
    int tid = threadIdx.x, warp = tid >> 5, lane = tid & 31;

    const float2* gb = g_big + ((size_t)bh*UU + ug*4)*LL;
    for (int i = tid; i < 4*LL; i += 512)
        p[i] = gb[i];
    __syncthreads();

    int su = warp >> 2, qt = warp & 3;
    float2* row = p + (su << 11) + (qt << 9);
    float mr = -3.4e38f, mi = -3.4e38f;
    #pragma unroll 8
    for (int k2 = 0; k2 < 16; ++k2) {
        float2 vv = row[lane + k2*32];
        mr = fmaxf(mr, vv.x); mi = fmaxf(mi, vv.y);
    }
    #pragma unroll
    for (int o = 16; o; o >>= 1) {
        mr = fmaxf(mr, __shfl_xor_sync(0xffffffffu, mr, o));
        mi = fmaxf(mi, __shfl_xor_sync(0xffffffffu, mi, o));
    }
    if (lane == 0) mxs[warp] = make_float2(mr, mi);
    __syncthreads();
    {
        float2 a = mxs[su*4], b = mxs[su*4+1], c = mxs[su*4+2], d = mxs[su*4+3];
        mr = fmaxf(fmaxf(a.x, b.x), fmaxf(c.x, d.x));
        mi = fmaxf(fmaxf(a.y, b.y), fmaxf(c.y, d.y));
    }
    __syncthreads();
    float sr = 0.f, si = 0.f;
    #pragma unroll 8
    for (int k2 = 0; k2 < 16; ++k2) {
        float2 vv = row[lane + k2*32];
        float er = __expf(vv.x - mr);
        float ei = __expf(vv.y - mi);
        row[lane + k2*32] = make_float2(er, ei);
        sr += er; si += ei;
    }
    #pragma unroll
    for (int o = 16; o; o >>= 1) {
        sr += __shfl_xor_sync(0xffffffffu, sr, o);
        si += __shfl_xor_sync(0xffffffffu, si, o);
    }
    if (lane == 0) mxs[warp] = make_float2(sr, si);
    __syncthreads();
    {
        float2 a = mxs[su*4], b = mxs[su*4+1], c = mxs[su*4+2], d = mxs[su*4+3];
        float inr = 1.0f / (a.x + b.x + c.x + d.x);
        float ini = 1.0f / (a.y + b.y + c.y + d.y);
        #pragma unroll 8
        for (int k2 = 0; k2 < 16; ++k2) {
            float2 vv = row[lane + k2*32];
            row[lane + k2*32] = make_float2(vv.x * inr, vv.y * ini);
        }
    }
    __syncthreads();

    float aR[4], aI[4];
    #pragma unroll
    for (int u = 0; u < 4; ++u) { aR[u]=0.f; aI[u]=0.f; }
    const float2* vb = g_vf + (size_t)bh*LL*EE;
    for (int l = warp; l < LL; l += 16) {
        float2 v2 = vb[(size_t)l*EE + lane];
        #pragma unroll
        for (int u = 0; u < 4; ++u) {
            float2 pp = p[(u << 11) + l];
            aR[u] = fmaf(pp.x, v2.x, aR[u]);
            aI[u] = fmaf(pp.y, v2.y, aI[u]);
        }
    }
    float s32[4];
    #pragma unroll
    for (int u = 0; u < 4; ++u) s32[u] = 0.f;
    for (int l = tid; l < LL; l += 512) {
        float v32r = vb[(size_t)l*EE + 32].x;
        #pragma unroll
        for (int u = 0; u < 4; ++u)
            s32[u] = fmaf(p[(u << 11) + l].x, v32r, s32[u]);
    }
    #pragma unroll
    for (int o = 16; o; o >>= 1) {
        #pragma unroll
        for (int u = 0; u < 4; ++u)
            s32[u] += __shfl_xor_sync(0xffffffffu, s32[u], o);
    }
    #pragma unroll
    for (int u = 0; u < 4; ++u) {
        accs[(warp*4 + u)*EE + lane] = make_float2(aR[u], aI[u]);
        if (lane == 0) accs[(warp*4 + u)*EE + 32] = make_float2(s32[u], 0.f);
    }
    __syncthreads();
    for (int t = tid; t < 4*EE; t += 512) {
        int u = t / EE, e = t - u*EE;
        float ssr = 0.f, ssi = 0.f;
        #pragma unroll
        for (int w = 0; w < 16; ++w) {
            float2 a = accs[(w*4 + u)*EE + e];
            ssr += a.x; ssi += a.y;
        }
        g_upd[((size_t)bh*UU + ug*4 + u)*EE + e] = make_float2(ssr, ssi);
    }
}

// ---------------- K7: scatter + irfft, 4 rows per warp ----------------
__global__ void k_out(float* __restrict__ out)
{
    __shared__ float tc[64], ts[64];
    __shared__ float2 ub[8][EE];
    int tid = threadIdx.x;
    if (tid < 64) {
        float s, c;
        sincospif(tid * (1.0f/32.0f), &s, &c);
        tc[tid] = c; ts[tid] = s;
    }
    __syncthreads();
    int warp = tid >> 5, lane = tid & 31;
    #pragma unroll 1
    for (int i = 0; i < 4; ++i) {
        int r = blockIdx.x * 32 + warp * 4 + i;
        int bh = r >> 11;
        int slot = g_slot[r];
        float* op = out + (size_t)r * DD;
        if (slot < 0) {
            op[lane]      = g_vmt[bh*DD + lane];
            op[lane + 32] = g_vmt[bh*DD + lane + 32];
        } else {
            const float2* X = g_upd + ((size_t)bh*UU + slot)*EE;
            ub[warp][lane] = X[lane];
            if (lane == 0) ub[warp][32] = X[32];
            __syncwarp();
            float a0 = ub[warp][0].x;
            float a32 = ub[warp][32].x;
            float sgn = (lane & 1) ? -a32 : a32;
            float acc1 = a0 + sgn, acc2 = a0 + sgn;
            #pragma unroll
            for (int e = 1; e < 32; ++e) {
                float2 Xe = ub[warp][e];
                int j1 = (e * lane) & 63;
                int j2 = (e * (lane + 32)) & 63;
                acc1 += 2.f * (Xe.x*tc[j1] - Xe.y*ts[j1]);
                acc2 += 2.f * (Xe.x*tc[j2] - Xe.y*ts[j2]);
            }
            op[lane]      = acc1 * (1.0f/64.0f);
            op[lane + 32] = acc2 * (1.0f/64.0f);
            __syncwarp();
        }
    }
}

// ---------------- launch ----------------
extern "C" void kernel_launch(void* const* d_in, const int* in_sizes, int n_in,
                              void* d_out, int out_size)
{
    (void)in_sizes; (void)n_in; (void)out_size;
    const float* q = (const float*)d_in[0];
    const float* k = (const float*)d_in[1];
    const float* v = (const float*)d_in[2];
    const int* isamp = (const int*)d_in[4];
    float* out = (float*)d_out;

    cudaFuncSetAttribute(k_msample, cudaFuncAttributeMaxDynamicSharedMemorySize, MS_SMEM);
    cudaFuncSetAttribute(k_smupd,   cudaFuncAttributeMaxDynamicSharedMemorySize, SMU_SMEM);

    k_rfft     <<<dim3(ROWS/32, 3), 256>>>(q, k, v);
    k_vmt      <<<BHN, 512>>>(v);
    k_msample  <<<dim3(LL/256, BHN), 1024, MS_SMEM>>>(isamp);
    k_topk     <<<BHN, 256>>>();
    k_scores   <<<dim3(4, 4, BHN), 512>>>();
    k_smupd    <<<dim3(10, BHN), 512, SMU_SMEM>>>();
    k_out      <<<ROWS/32, 256>>>(out);
}

// round 12
// speedup vs baseline: 1.3559x; 1.0051x over previous
#include <cuda_runtime.h>
#include <cstdint>
#include <cstddef>

#define BB 8
#define LL 2048
#define HH 8
#define DD 64
#define EE 33
#define UU 40
#define SK 40
#define BHN (BB*HH)
#define ROWS (BHN*LL)

// ---------------- static scratch ----------------
__device__ float2 g_qf [ROWS*EE];
__device__ float2 g_vf [ROWS*EE];
__device__ float4 g_kfC[(size_t)BHN*8*4096];   // [bh][chunk(8)][id*2+half]
__device__ float  g_k32[BHN*LL];
__device__ float  g_M  [ROWS];
__device__ int    g_top [BHN*UU];
__device__ int    g_slot[ROWS];
__device__ float2 g_upd [BHN*UU*EE];
__device__ float  g_vmt[BHN*DD];
__device__ float2 g_big [(size_t)BHN*UU*LL];

__device__ __forceinline__ void cpa16(void* s, const void* g) {
    unsigned sa = (unsigned)__cvta_generic_to_shared(s);
    asm volatile("cp.async.cg.shared.global [%0], [%1], 16;" :: "r"(sa), "l"(g));
}
__device__ __forceinline__ void cp_commit() {
    asm volatile("cp.async.commit_group;" ::: "memory");
}
__device__ __forceinline__ void cp_wait1() {
    asm volatile("cp.async.wait_group 1;" ::: "memory");
}
__device__ __forceinline__ void cp_wait0() {
    asm volatile("cp.async.wait_group 0;" ::: "memory");
}

// ---------------- K1: rfft, 4 rows per warp; k-branch writes chunked layout ----------------
__global__ void k_rfft(const float* __restrict__ q,
                       const float* __restrict__ k,
                       const float* __restrict__ v)
{
    __shared__ float2 w32t[16], w64t[32];
    __shared__ float2 zs[8][32];
    int tid = threadIdx.x;
    if (tid < 16) {
        float s, c;
        sincospif(tid * (1.0f/16.0f), &s, &c);
        w32t[tid] = make_float2(c, s);
    } else if (tid < 48) {
        float s, c;
        sincospif((tid - 16) * (1.0f/32.0f), &s, &c);
        w64t[tid - 16] = make_float2(c, s);
    }
    __syncthreads();
    int warp = tid >> 5, lane = tid & 31;
    int which = blockIdx.y;
    const float* src = (which == 0) ? q : (which == 1) ? k : v;
    float2* out = (which == 0) ? g_qf : g_vf;
    #pragma unroll 1
    for (int i = 0; i < 4; ++i) {
        int r  = blockIdx.x * 32 + warp * 4 + i;
        int l  = r & (LL - 1);
        int bh = r >> 11;
        int b = bh >> 3, h = bh & 7;
        const float2* x2 = (const float2*)(src + (((size_t)b*LL + l)*HH + h) * DD);
        float2 z = x2[lane];
        float zr = z.x, zi = z.y;
        #pragma unroll
        for (int s = 0; s < 5; ++s) {
            int hm = 16 >> s;
            float orr = __shfl_xor_sync(0xffffffffu, zr, hm);
            float oii = __shfl_xor_sync(0xffffffffu, zi, hm);
            float2 w = w32t[(lane & (hm - 1)) << s];
            float dx = orr - zr, dy = oii - zi;
            float hr = dx*w.x + dy*w.y;
            float hi = dy*w.x - dx*w.y;
            float lr = zr + orr, li = zi + oii;
            bool top = (lane & hm) != 0;
            zr = top ? hr : lr;
            zi = top ? hi : li;
        }
        int bin = __brev((unsigned)lane) >> 27;
        zs[warp][bin] = make_float2(zr, zi);
        __syncwarp();
        float2 m = zs[warp][(32 - bin) & 31];
        __syncwarp();
        float Zer = 0.5f*(zr + m.x), Zei = 0.5f*(zi - m.y);
        float Zor = 0.5f*(zi + m.y), Zoi = -0.5f*(zr - m.x);
        float2 w = w64t[bin];
        float Xr = Zer + w.x*Zor + w.y*Zoi;
        float Xi = Zei + w.x*Zoi - w.y*Zor;
        if (which == 1) {
            int c = bin >> 2, half = (bin >> 1) & 1;
            float2* kc2 = (float2*)g_kfC;
            size_t idx = ((((size_t)(bh*8 + c)) << 12) + (size_t)l*2 + half)*2 + (bin & 1);
            kc2[idx] = make_float2(Xr, Xi);
            if (bin == 0) g_k32[bh*LL + l] = zr - zi;
        } else {
            out[(size_t)r*EE + bin] = make_float2(Xr, Xi);
            if (bin == 0) out[(size_t)r*EE + 32] = make_float2(zr - zi, 0.f);
        }
    }
}

// ---------------- K2b: time-domain v mean ----------------
__global__ void k_vmt(const float* __restrict__ v)
{
    __shared__ float part[8][64];
    int bh = blockIdx.x, b = bh >> 3, h = bh & 7;
    int tid = threadIdx.x;
    int d = tid & 63, g = tid >> 6;
    const float* base = v + (((size_t)b*LL)*HH + h) * DD + d;
    float acc = 0.f;
    #pragma unroll 8
    for (int i = g; i < LL; i += 8) acc += base[(size_t)i * (HH*DD)];
    part[g][d] = acc;
    __syncthreads();
    if (tid < 64) {
        float s = 0.f;
        #pragma unroll
        for (int g2 = 0; g2 < 8; ++g2) s += part[g2][tid];
        g_vmt[bh*DD + tid] = s * (1.0f/LL);
    }
}

// ---------------- K3: sampled QK -> M (smem keys + staged q) ----------------
#define MS_KBUF   131072
#define MS_SK32   (MS_KBUF)
#define MS_PT     (MS_KBUF + 8192)
#define MS_QS     (MS_KBUF + 8192 + 16384)
#define MS_SMEM   (MS_KBUF + 8192 + 16384 + 10240)
__global__ void __launch_bounds__(1024, 1) k_msample(const int* __restrict__ isamp)
{
    extern __shared__ char sm[];
    float4* kbuf = (float4*)sm;
    float*  sk32 = (float*)(sm + MS_SK32);
    float4* pt   = (float4*)(sm + MS_PT);
    float2* qs   = (float2*)(sm + MS_QS);

    int tid = threadIdx.x;
    int l0  = blockIdx.x * 256;
    int bh  = blockIdx.y;
    int sg  = tid & 3;
    int lq  = tid >> 2;
    int l   = l0 + lq;

    sk32[tid]        = g_k32[bh*LL + tid];
    sk32[tid + 1024] = g_k32[bh*LL + tid + 1024];

    const int* ip = isamp + l*SK + sg*10;
    int ids[10];
    #pragma unroll
    for (int i = 0; i < 10; ++i) ids[i] = ip[i];

    float q32 = g_qf[((size_t)(bh*LL + l))*EE + 32].x;

    const float4* kc = g_kfC + (((size_t)(bh*8)) << 12);
    #pragma unroll
    for (int it = 0; it < 4; ++it) {
        int lin = it*1024 + tid;
        int sw  = lin ^ ((lin >> 3) & 7);
        cpa16(&kbuf[sw], &kc[lin]);
    }
    cp_commit();

    float accR[10], accI[10];
    #pragma unroll
    for (int s = 0; s < 10; ++s) { accR[s] = 0.f; accI[s] = 0.f; }

    int qrow_s = tid >> 2, qbin_s = tid & 3;
    const float2* qsrc = g_qf + (size_t)(bh*LL + l0 + qrow_s)*EE + qbin_s;

    #pragma unroll 1
    for (int c = 0; c < 8; ++c) {
        qs[qrow_s*5 + qbin_s] = qsrc[4*c];
        int cur = (c & 1) << 12;
        if (c < 7) {
            const float4* src = kc + ((size_t)(c+1) << 12);
            int nb = ((c+1) & 1) << 12;
            #pragma unroll
            for (int it = 0; it < 4; ++it) {
                int lin = it*1024 + tid;
                int sw  = lin ^ ((lin >> 3) & 7);
                cpa16(&kbuf[nb + sw], &src[lin]);
            }
            cp_commit();
            cp_wait1();
        } else {
            cp_wait0();
        }
        __syncthreads();
        float2 q0 = qs[lq*5 + 0], q1 = qs[lq*5 + 1], q2 = qs[lq*5 + 2], q3 = qs[lq*5 + 3];
        #pragma unroll
        for (int s = 0; s < 10; ++s) {
            int id = ids[s];
            int p = id << 1, x = (id >> 2) & 7;
            float4 h0 = kbuf[cur + (p ^ x)];
            float4 h1 = kbuf[cur + ((p + 1) ^ x)];
            accR[s] = fmaf(q0.x, h0.x, accR[s]); accR[s] = fmaf(-q0.y, h0.y, accR[s]);
            accI[s] = fmaf(q0.x, h0.y, accI[s]); accI[s] = fmaf( q0.y, h0.x, accI[s]);
            accR[s] = fmaf(q1.x, h0.z, accR[s]); accR[s] = fmaf(-q1.y, h0.w, accR[s]);
            accI[s] = fmaf(q1.x, h0.w, accI[s]); accI[s] = fmaf( q1.y, h0.z, accI[s]);
            accR[s] = fmaf(q2.x, h1.x, accR[s]); accR[s] = fmaf(-q2.y, h1.y, accR[s]);
            accI[s] = fmaf(q2.x, h1.y, accI[s]); accI[s] = fmaf( q2.y, h1.x, accI[s]);
            accR[s] = fmaf(q3.x, h1.z, accR[s]); accR[s] = fmaf(-q3.y, h1.w, accR[s]);
            accI[s] = fmaf(q3.x, h1.w, accI[s]); accI[s] = fmaf( q3.y, h1.z, accI[s]);
        }
        __syncthreads();
    }
    #pragma unroll
    for (int s = 0; s < 10; ++s)
        accR[s] = fmaf(q32, sk32[ids[s]], accR[s]);

    float mr = -3.4e38f, mi = -3.4e38f, sr = 0.f, si = 0.f;
    #pragma unroll
    for (int s = 0; s < 10; ++s) {
        mr = fmaxf(mr, accR[s]); mi = fmaxf(mi, accI[s]);
        sr += accR[s];           si += accI[s];
    }
    pt[sg*256 + lq] = make_float4(mr, mi, sr, si);
    __syncthreads();
    if (tid < 256) {
        float4 a = pt[tid], b = pt[256 + tid], c2 = pt[512 + tid], d = pt[768 + tid];
        float MR = fmaxf(fmaxf(a.x, b.x), fmaxf(c2.x, d.x));
        float MI = fmaxf(fmaxf(a.y, b.y), fmaxf(c2.y, d.y));
        float SR = a.z + b.z + c2.z + d.z;
        float SI = a.w + b.w + c2.w + d.w;
        g_M[(size_t)bh*LL + l0 + tid] = MR + MI - (SR + SI) * (1.0f/LL);
    }
}

// ---------------- K4: top-40 per bh — warp-local select + single-warp merge ----------------
__global__ void __launch_bounds__(256) k_topk()
{
    __shared__ float wlv[8][UU];
    __shared__ int   wli[8][UU];
    int bh = blockIdx.x, tid = threadIdx.x, lane = tid & 31, warp = tid >> 5;
    // init slot map
    for (int i = tid; i < LL; i += 256)
        g_slot[bh*LL + i] = -1;

    // phase 1: warp w owns contiguous [w*256, w*256+256); 8 values per lane in regs
    int base = warp * 256;
    float vals[8];
    #pragma unroll
    for (int k = 0; k < 8; ++k)
        vals[k] = g_M[bh*LL + base + lane + k*32];
    #pragma unroll 1
    for (int u = 0; u < UU; ++u) {
        float best = -3.4e38f; int bk = 0;
        #pragma unroll
        for (int k = 0; k < 8; ++k)
            if (vals[k] > best) { best = vals[k]; bk = k; }   // first win = lowest idx
        int bidx = base + lane + bk*32;
        float bv = best; int bi = bidx;
        #pragma unroll
        for (int o = 16; o; o >>= 1) {
            float ov = __shfl_xor_sync(0xffffffffu, bv, o);
            int   oi = __shfl_xor_sync(0xffffffffu, bi, o);
            if (ov > bv || (ov == bv && oi < bi)) { bv = ov; bi = oi; }
        }
        if (bi == bidx) vals[bk] = -3.4e38f;   // unique winner clears its slot
        if (lane == 0) { wlv[warp][u] = bv; wli[warp][u] = bi; }
    }
    __syncthreads();

    // phase 2: warp 0 merges 8 descending lists
    if (warp == 0) {
        int ptr = 0;
        #pragma unroll 1
        for (int u = 0; u < UU; ++u) {
            float hv = (lane < 8) ? wlv[lane][ptr] : -3.4e38f;
            int   hi = (lane < 8) ? wli[lane][ptr] : (1 << 30);
            float rv = hv; int ri = hi;
            #pragma unroll
            for (int o = 4; o; o >>= 1) {
                float ov = __shfl_xor_sync(0xffffffffu, rv, o);
                int   oi = __shfl_xor_sync(0xffffffffu, ri, o);
                if (ov > rv || (ov == rv && oi < ri)) { rv = ov; ri = oi; }
            }
            // broadcast winner to all lanes (lanes 8..31 already have -inf heads)
            rv = __shfl_sync(0xffffffffu, rv, 0);
            ri = __shfl_sync(0xffffffffu, ri, 0);
            if (lane < 8 && ri == hi) ptr++;
            if (lane == 0) {
                g_top[bh*UU + u] = ri;
                g_slot[bh*LL + ri] = u;
            }
        }
    }
}

// ---------------- K5: full scores from chunked keys, 10-u register blocked ----------------
__global__ void __launch_bounds__(512) k_scores()
{
    __shared__ float2 shq[10][EE];
    int bh = blockIdx.z;
    int ug = blockIdx.y;
    int jt = blockIdx.x;
    int tid = threadIdx.x;
    for (int t = tid; t < 10*EE; t += 512) {
        int ul = t / EE, e = t - ul*EE;
        int qi = g_top[bh*UU + ug*10 + ul];
        shq[ul][e] = g_qf[((size_t)bh*LL + qi)*EE + e];
    }
    __syncthreads();
    int j = jt*512 + tid;
    float accR[10], accI[10];
    #pragma unroll
    for (int u = 0; u < 10; ++u) { accR[u] = 0.f; accI[u] = 0.f; }
    const float4* kc = g_kfC + (((size_t)(bh*8)) << 12);
    #pragma unroll 1
    for (int c = 0; c < 8; ++c) {
        float4 h0 = kc[((size_t)c << 12) + j*2];
        float4 h1 = kc[((size_t)c << 12) + j*2 + 1];
        #pragma unroll
        for (int u = 0; u < 10; ++u) {
            float2 q0 = shq[u][4*c], q1 = shq[u][4*c+1], q2 = shq[u][4*c+2], q3 = shq[u][4*c+3];
            accR[u] = fmaf(q0.x, h0.x, accR[u]); accR[u] = fmaf(-q0.y, h0.y, accR[u]);
            accI[u] = fmaf(q0.x, h0.y, accI[u]); accI[u] = fmaf( q0.y, h0.x, accI[u]);
            accR[u] = fmaf(q1.x, h0.z, accR[u]); accR[u] = fmaf(-q1.y, h0.w, accR[u]);
            accI[u] = fmaf(q1.x, h0.w, accI[u]); accI[u] = fmaf( q1.y, h0.z, accI[u]);
            accR[u] = fmaf(q2.x, h1.x, accR[u]); accR[u] = fmaf(-q2.y, h1.y, accR[u]);
            accI[u] = fmaf(q2.x, h1.y, accI[u]); accI[u] = fmaf( q2.y, h1.x, accI[u]);
            accR[u] = fmaf(q3.x, h1.z, accR[u]); accR[u] = fmaf(-q3.y, h1.w, accR[u]);
            accI[u] = fmaf(q3.x, h1.w, accI[u]); accI[u] = fmaf( q3.y, h1.z, accI[u]);
        }
    }
    {
        float k32 = g_k32[bh*LL + j];
        #pragma unroll
        for (int u = 0; u < 10; ++u) {
            float2 qv = shq[u][32];
            accR[u] = fmaf(qv.x, k32, accR[u]);
            accI[u] = fmaf(qv.y, k32, accI[u]);
        }
    }
    const float sc = 0.125f;
    #pragma unroll
    for (int u = 0; u < 10; ++u)
        g_big[((size_t)bh*UU + ug*10 + u)*LL + j] = make_float2(accR[u]*sc, accI[u]*sc);
}

// ---------------- K6: fused softmax + upd (4 u per block, 2 blocks/SM) ----------------
#define SMU_SMEM (65536 + 16896 + 128)
__global__ void __launch_bounds__(512) k_smupd()
{
    extern __shared__ char smc[];
    float2* p    = (float2*)smc;
    float2* accs = (float2*)(smc + 65536);
    float2* mxs  = (float2*)(smc + 65536 + 16896);
    int bh = blockIdx.y, ug = blockIdx.x;
    int tid = threadIdx.x, warp = tid >> 5, lane = tid & 31;

    const float2* gb = g_big + ((size_t)bh*UU + ug*4)*LL;
    for (int i = tid; i < 4*LL; i += 512)
        p[i] = gb[i];
    __syncthreads();

    int su = warp >> 2, qt = warp & 3;
    float2* row = p + (su << 11) + (qt << 9);
    float mr = -3.4e38f, mi = -3.4e38f;
    #pragma unroll 8
    for (int k2 = 0; k2 < 16; ++k2) {
        float2 vv = row[lane + k2*32];
        mr = fmaxf(mr, vv.x); mi = fmaxf(mi, vv.y);
    }
    #pragma unroll
    for (int o = 16; o; o >>= 1) {
        mr = fmaxf(mr, __shfl_xor_sync(0xffffffffu, mr, o));
        mi = fmaxf(mi, __shfl_xor_sync(0xffffffffu, mi, o));
    }
    if (lane == 0) mxs[warp] = make_float2(mr, mi);
    __syncthreads();
    {
        float2 a = mxs[su*4], b = mxs[su*4+1], c = mxs[su*4+2], d = mxs[su*4+3];
        mr = fmaxf(fmaxf(a.x, b.x), fmaxf(c.x, d.x));
        mi = fmaxf(fmaxf(a.y, b.y), fmaxf(c.y, d.y));
    }
    __syncthreads();
    float sr = 0.f, si = 0.f;
    #pragma unroll 8
    for (int k2 = 0; k2 < 16; ++k2) {
        float2 vv = row[lane + k2*32];
        float er = __expf(vv.x - mr);
        float ei = __expf(vv.y - mi);
        row[lane + k2*32] = make_float2(er, ei);
        sr += er; si += ei;
    }
    #pragma unroll
    for (int o = 16; o; o >>= 1) {
        sr += __shfl_xor_sync(0xffffffffu, sr, o);
        si += __shfl_xor_sync(0xffffffffu, si, o);
    }
    if (lane == 0) mxs[warp] = make_float2(sr, si);
    __syncthreads();
    {
        float2 a = mxs[su*4], b = mxs[su*4+1], c = mxs[su*4+2], d = mxs[su*4+3];
        float inr = 1.0f / (a.x + b.x + c.x + d.x);
        float ini = 1.0f / (a.y + b.y + c.y + d.y);
        #pragma unroll 8
        for (int k2 = 0; k2 < 16; ++k2) {
            float2 vv = row[lane + k2*32];
            row[lane + k2*32] = make_float2(vv.x * inr, vv.y * ini);
        }
    }
    __syncthreads();

    float aR[4], aI[4];
    #pragma unroll
    for (int u = 0; u < 4; ++u) { aR[u]=0.f; aI[u]=0.f; }
    const float2* vb = g_vf + (size_t)bh*LL*EE;
    for (int l = warp; l < LL; l += 16) {
        float2 v2 = vb[(size_t)l*EE + lane];
        #pragma unroll
        for (int u = 0; u < 4; ++u) {
            float2 pp = p[(u << 11) + l];
            aR[u] = fmaf(pp.x, v2.x, aR[u]);
            aI[u] = fmaf(pp.y, v2.y, aI[u]);
        }
    }
    float s32[4];
    #pragma unroll
    for (int u = 0; u < 4; ++u) s32[u] = 0.f;
    for (int l = tid; l < LL; l += 512) {
        float v32r = vb[(size_t)l*EE + 32].x;
        #pragma unroll
        for (int u = 0; u < 4; ++u)
            s32[u] = fmaf(p[(u << 11) + l].x, v32r, s32[u]);
    }
    #pragma unroll
    for (int o = 16; o; o >>= 1) {
        #pragma unroll
        for (int u = 0; u < 4; ++u)
            s32[u] += __shfl_xor_sync(0xffffffffu, s32[u], o);
    }
    #pragma unroll
    for (int u = 0; u < 4; ++u) {
        accs[(warp*4 + u)*EE + lane] = make_float2(aR[u], aI[u]);
        if (lane == 0) accs[(warp*4 + u)*EE + 32] = make_float2(s32[u], 0.f);
    }
    __syncthreads();
    for (int t = tid; t < 4*EE; t += 512) {
        int u = t / EE, e = t - u*EE;
        float ssr = 0.f, ssi = 0.f;
        #pragma unroll
        for (int w = 0; w < 16; ++w) {
            float2 a = accs[(w*4 + u)*EE + e];
            ssr += a.x; ssi += a.y;
        }
        g_upd[((size_t)bh*UU + ug*4 + u)*EE + e] = make_float2(ssr, ssi);
    }
}

// ---------------- K7: scatter + irfft, 4 rows per warp ----------------
__global__ void k_out(float* __restrict__ out)
{
    __shared__ float tc[64], ts[64];
    __shared__ float2 ub[8][EE];
    int tid = threadIdx.x;
    if (tid < 64) {
        float s, c;
        sincospif(tid * (1.0f/32.0f), &s, &c);
        tc[tid] = c; ts[tid] = s;
    }
    __syncthreads();
    int warp = tid >> 5, lane = tid & 31;
    #pragma unroll 1
    for (int i = 0; i < 4; ++i) {
        int r = blockIdx.x * 32 + warp * 4 + i;
        int bh = r >> 11;
        int slot = g_slot[r];
        float* op = out + (size_t)r * DD;
        if (slot < 0) {
            op[lane]      = g_vmt[bh*DD + lane];
            op[lane + 32] = g_vmt[bh*DD + lane + 32];
        } else {
            const float2* X = g_upd + ((size_t)bh*UU + slot)*EE;
            ub[warp][lane] = X[lane];
            if (lane == 0) ub[warp][32] = X[32];
            __syncwarp();
            float a0 = ub[warp][0].x;
            float a32 = ub[warp][32].x;
            float sgn = (lane & 1) ? -a32 : a32;
            float acc1 = a0 + sgn, acc2 = a0 + sgn;
            #pragma unroll
            for (int e = 1; e < 32; ++e) {
                float2 Xe = ub[warp][e];
                int j1 = (e * lane) & 63;
                int j2 = (e * (lane + 32)) & 63;
                acc1 += 2.f * (Xe.x*tc[j1] - Xe.y*ts[j1]);
                acc2 += 2.f * (Xe.x*tc[j2] - Xe.y*ts[j2]);
            }
            op[lane]      = acc1 * (1.0f/64.0f);
            op[lane + 32] = acc2 * (1.0f/64.0f);
            __syncwarp();
        }
    }
}

// ---------------- launch ----------------
extern "C" void kernel_launch(void* const* d_in, const int* in_sizes, int n_in,
                              void* d_out, int out_size)
{
    (void)in_sizes; (void)n_in; (void)out_size;
    const float* q = (const float*)d_in[0];
    const float* k = (const float*)d_in[1];
    const float* v = (const float*)d_in[2];
    const int* isamp = (const int*)d_in[4];
    float* out = (float*)d_out;

    cudaFuncSetAttribute(k_msample, cudaFuncAttributeMaxDynamicSharedMemorySize, MS_SMEM);
    cudaFuncSetAttribute(k_smupd,   cudaFuncAttributeMaxDynamicSharedMemorySize, SMU_SMEM);

    k_rfft     <<<dim3(ROWS/32, 3), 256>>>(q, k, v);
    k_vmt      <<<BHN, 512>>>(v);
    k_msample  <<<dim3(LL/256, BHN), 1024, MS_SMEM>>>(isamp);
    k_topk     <<<BHN, 256>>>();
    k_scores   <<<dim3(4, 4, BHN), 512>>>();
    k_smupd    <<<dim3(10, BHN), 512, SMU_SMEM>>>();
    k_out      <<<ROWS/32, 256>>>(out);
}

// round 13
// speedup vs baseline: 1.3601x; 1.0031x over previous
#include <cuda_runtime.h>
#include <cstdint>
#include <cstddef>

#define BB 8
#define LL 2048
#define HH 8
#define DD 64
#define EE 33
#define UU 40
#define SK 40
#define BHN (BB*HH)
#define ROWS (BHN*LL)

// ---------------- static scratch ----------------
__device__ float2 g_qf [ROWS*EE];
__device__ float2 g_vf [ROWS*EE];
__device__ float4 g_kfC[(size_t)BHN*8*4096];   // [bh][chunk(8)][id*2+half]
__device__ float  g_k32[BHN*LL];
__device__ float  g_M  [ROWS];
__device__ int    g_top [BHN*UU];
__device__ int    g_slot[ROWS];
__device__ float2 g_upd [BHN*UU*EE];
__device__ float  g_vmt[BHN*DD];
__device__ float2 g_big [(size_t)BHN*UU*LL];

__device__ __forceinline__ void cpa16(void* s, const void* g) {
    unsigned sa = (unsigned)__cvta_generic_to_shared(s);
    asm volatile("cp.async.cg.shared.global [%0], [%1], 16;" :: "r"(sa), "l"(g));
}
__device__ __forceinline__ void cp_commit() {
    asm volatile("cp.async.commit_group;" ::: "memory");
}
__device__ __forceinline__ void cp_wait1() {
    asm volatile("cp.async.wait_group 1;" ::: "memory");
}
__device__ __forceinline__ void cp_wait0() {
    asm volatile("cp.async.wait_group 0;" ::: "memory");
}

// ---------------- K1: rfft, 4 rows/warp, register twiddles, shfl mirror ----------------
__global__ void k_rfft(const float* __restrict__ q,
                       const float* __restrict__ k,
                       const float* __restrict__ v)
{
    __shared__ float2 w32t[16], w64t[32];
    int tid = threadIdx.x;
    if (tid < 16) {
        float s, c;
        sincospif(tid * (1.0f/16.0f), &s, &c);
        w32t[tid] = make_float2(c, s);
    } else if (tid < 48) {
        float s, c;
        sincospif((tid - 16) * (1.0f/32.0f), &s, &c);
        w64t[tid - 16] = make_float2(c, s);
    }
    __syncthreads();
    int warp = tid >> 5, lane = tid & 31;
    // lane-invariant (per-row) precompute
    float2 tw[5];
    #pragma unroll
    for (int s = 0; s < 5; ++s) {
        int hm = 16 >> s;
        tw[s] = w32t[(lane & (hm - 1)) << s];
    }
    int bin = __brev((unsigned)lane) >> 27;
    float2 w64 = w64t[bin];
    int mb   = (32 - bin) & 31;
    int srcl = __brev((unsigned)mb) >> 27;   // lane holding mirror bin
    int which = blockIdx.y;
    const float* src = (which == 0) ? q : (which == 1) ? k : v;
    float2* out = (which == 0) ? g_qf : g_vf;
    #pragma unroll 1
    for (int i = 0; i < 4; ++i) {
        int r  = blockIdx.x * 32 + warp * 4 + i;
        int l  = r & (LL - 1);
        int bh = r >> 11;
        int b = bh >> 3, h = bh & 7;
        const float2* x2 = (const float2*)(src + (((size_t)b*LL + l)*HH + h) * DD);
        float2 z = x2[lane];
        float zr = z.x, zi = z.y;
        #pragma unroll
        for (int s = 0; s < 5; ++s) {
            int hm = 16 >> s;
            float orr = __shfl_xor_sync(0xffffffffu, zr, hm);
            float oii = __shfl_xor_sync(0xffffffffu, zi, hm);
            float2 w = tw[s];
            float dx = orr - zr, dy = oii - zi;
            float hr = dx*w.x + dy*w.y;
            float hi = dy*w.x - dx*w.y;
            float lr = zr + orr, li = zi + oii;
            bool top = (lane & hm) != 0;
            zr = top ? hr : lr;
            zi = top ? hi : li;
        }
        // mirror via shfl: lane srcl holds bin (32-bin)&31
        float Zmr = __shfl_sync(0xffffffffu, zr, srcl);
        float Zmi = __shfl_sync(0xffffffffu, zi, srcl);
        float Zer = 0.5f*(zr + Zmr), Zei = 0.5f*(zi - Zmi);
        float Zor = 0.5f*(zi + Zmi), Zoi = -0.5f*(zr - Zmr);
        float Xr = Zer + w64.x*Zor + w64.y*Zoi;
        float Xi = Zei + w64.x*Zoi - w64.y*Zor;
        if (which == 1) {
            int c = bin >> 2, half = (bin >> 1) & 1;
            float2* kc2 = (float2*)g_kfC;
            size_t idx = ((((size_t)(bh*8 + c)) << 12) + (size_t)l*2 + half)*2 + (bin & 1);
            kc2[idx] = make_float2(Xr, Xi);
            if (bin == 0) g_k32[bh*LL + l] = zr - zi;
        } else {
            out[(size_t)r*EE + bin] = make_float2(Xr, Xi);
            if (bin == 0) out[(size_t)r*EE + 32] = make_float2(zr - zi, 0.f);
        }
    }
}

// ---------------- K2b: time-domain v mean ----------------
__global__ void k_vmt(const float* __restrict__ v)
{
    __shared__ float part[8][64];
    int bh = blockIdx.x, b = bh >> 3, h = bh & 7;
    int tid = threadIdx.x;
    int d = tid & 63, g = tid >> 6;
    const float* base = v + (((size_t)b*LL)*HH + h) * DD + d;
    float acc = 0.f;
    #pragma unroll 8
    for (int i = g; i < LL; i += 8) acc += base[(size_t)i * (HH*DD)];
    part[g][d] = acc;
    __syncthreads();
    if (tid < 64) {
        float s = 0.f;
        #pragma unroll
        for (int g2 = 0; g2 < 8; ++g2) s += part[g2][tid];
        g_vmt[bh*DD + tid] = s * (1.0f/LL);
    }
}

// ---------------- K3: sampled QK -> M (smem keys + staged q) ----------------
#define MS_KBUF   131072
#define MS_SK32   (MS_KBUF)
#define MS_PT     (MS_KBUF + 8192)
#define MS_QS     (MS_KBUF + 8192 + 16384)
#define MS_SMEM   (MS_KBUF + 8192 + 16384 + 10240)
__global__ void __launch_bounds__(1024, 1) k_msample(const int* __restrict__ isamp)
{
    extern __shared__ char sm[];
    float4* kbuf = (float4*)sm;
    float*  sk32 = (float*)(sm + MS_SK32);
    float4* pt   = (float4*)(sm + MS_PT);
    float2* qs   = (float2*)(sm + MS_QS);

    int tid = threadIdx.x;
    int l0  = blockIdx.x * 256;
    int bh  = blockIdx.y;
    int sg  = tid & 3;
    int lq  = tid >> 2;
    int l   = l0 + lq;

    sk32[tid]        = g_k32[bh*LL + tid];
    sk32[tid + 1024] = g_k32[bh*LL + tid + 1024];

    const int* ip = isamp + l*SK + sg*10;
    int ids[10];
    #pragma unroll
    for (int i = 0; i < 10; ++i) ids[i] = ip[i];

    float q32 = g_qf[((size_t)(bh*LL + l))*EE + 32].x;

    const float4* kc = g_kfC + (((size_t)(bh*8)) << 12);
    #pragma unroll
    for (int it = 0; it < 4; ++it) {
        int lin = it*1024 + tid;
        int sw  = lin ^ ((lin >> 3) & 7);
        cpa16(&kbuf[sw], &kc[lin]);
    }
    cp_commit();

    float accR[10], accI[10];
    #pragma unroll
    for (int s = 0; s < 10; ++s) { accR[s] = 0.f; accI[s] = 0.f; }

    int qrow_s = tid >> 2, qbin_s = tid & 3;
    const float2* qsrc = g_qf + (size_t)(bh*LL + l0 + qrow_s)*EE + qbin_s;

    #pragma unroll 1
    for (int c = 0; c < 8; ++c) {
        qs[qrow_s*5 + qbin_s] = qsrc[4*c];
        int cur = (c & 1) << 12;
        if (c < 7) {
            const float4* src = kc + ((size_t)(c+1) << 12);
            int nb = ((c+1) & 1) << 12;
            #pragma unroll
            for (int it = 0; it < 4; ++it) {
                int lin = it*1024 + tid;
                int sw  = lin ^ ((lin >> 3) & 7);
                cpa16(&kbuf[nb + sw], &src[lin]);
            }
            cp_commit();
            cp_wait1();
        } else {
            cp_wait0();
        }
        __syncthreads();
        float2 q0 = qs[lq*5 + 0], q1 = qs[lq*5 + 1], q2 = qs[lq*5 + 2], q3 = qs[lq*5 + 3];
        #pragma unroll
        for (int s = 0; s < 10; ++s) {
            int id = ids[s];
            int p = id << 1, x = (id >> 2) & 7;
            float4 h0 = kbuf[cur + (p ^ x)];
            float4 h1 = kbuf[cur + ((p + 1) ^ x)];
            accR[s] = fmaf(q0.x, h0.x, accR[s]); accR[s] = fmaf(-q0.y, h0.y, accR[s]);
            accI[s] = fmaf(q0.x, h0.y, accI[s]); accI[s] = fmaf( q0.y, h0.x, accI[s]);
            accR[s] = fmaf(q1.x, h0.z, accR[s]); accR[s] = fmaf(-q1.y, h0.w, accR[s]);
            accI[s] = fmaf(q1.x, h0.w, accI[s]); accI[s] = fmaf( q1.y, h0.z, accI[s]);
            accR[s] = fmaf(q2.x, h1.x, accR[s]); accR[s] = fmaf(-q2.y, h1.y, accR[s]);
            accI[s] = fmaf(q2.x, h1.y, accI[s]); accI[s] = fmaf( q2.y, h1.x, accI[s]);
            accR[s] = fmaf(q3.x, h1.z, accR[s]); accR[s] = fmaf(-q3.y, h1.w, accR[s]);
            accI[s] = fmaf(q3.x, h1.w, accI[s]); accI[s] = fmaf( q3.y, h1.z, accI[s]);
        }
        __syncthreads();
    }
    #pragma unroll
    for (int s = 0; s < 10; ++s)
        accR[s] = fmaf(q32, sk32[ids[s]], accR[s]);

    float mr = -3.4e38f, mi = -3.4e38f, sr = 0.f, si = 0.f;
    #pragma unroll
    for (int s = 0; s < 10; ++s) {
        mr = fmaxf(mr, accR[s]); mi = fmaxf(mi, accI[s]);
        sr += accR[s];           si += accI[s];
    }
    pt[sg*256 + lq] = make_float4(mr, mi, sr, si);
    __syncthreads();
    if (tid < 256) {
        float4 a = pt[tid], b = pt[256 + tid], c2 = pt[512 + tid], d = pt[768 + tid];
        float MR = fmaxf(fmaxf(a.x, b.x), fmaxf(c2.x, d.x));
        float MI = fmaxf(fmaxf(a.y, b.y), fmaxf(c2.y, d.y));
        float SR = a.z + b.z + c2.z + d.z;
        float SI = a.w + b.w + c2.w + d.w;
        g_M[(size_t)bh*LL + l0 + tid] = MR + MI - (SR + SI) * (1.0f/LL);
    }
}

// ---------------- K4: top-40 per bh — warp-local select + single-warp merge ----------------
__global__ void __launch_bounds__(256) k_topk()
{
    __shared__ float wlv[8][UU];
    __shared__ int   wli[8][UU];
    int bh = blockIdx.x, tid = threadIdx.x, lane = tid & 31, warp = tid >> 5;
    for (int i = tid; i < LL; i += 256)
        g_slot[bh*LL + i] = -1;

    int base = warp * 256;
    float vals[8];
    #pragma unroll
    for (int k = 0; k < 8; ++k)
        vals[k] = g_M[bh*LL + base + lane + k*32];
    #pragma unroll 1
    for (int u = 0; u < UU; ++u) {
        float best = -3.4e38f; int bk = 0;
        #pragma unroll
        for (int k = 0; k < 8; ++k)
            if (vals[k] > best) { best = vals[k]; bk = k; }
        int bidx = base + lane + bk*32;
        float bv = best; int bi = bidx;
        #pragma unroll
        for (int o = 16; o; o >>= 1) {
            float ov = __shfl_xor_sync(0xffffffffu, bv, o);
            int   oi = __shfl_xor_sync(0xffffffffu, bi, o);
            if (ov > bv || (ov == bv && oi < bi)) { bv = ov; bi = oi; }
        }
        if (bi == bidx) vals[bk] = -3.4e38f;
        if (lane == 0) { wlv[warp][u] = bv; wli[warp][u] = bi; }
    }
    __syncthreads();

    if (warp == 0) {
        int ptr = 0;
        #pragma unroll 1
        for (int u = 0; u < UU; ++u) {
            float hv = (lane < 8) ? wlv[lane][ptr] : -3.4e38f;
            int   hi = (lane < 8) ? wli[lane][ptr] : (1 << 30);
            float rv = hv; int ri = hi;
            #pragma unroll
            for (int o = 4; o; o >>= 1) {
                float ov = __shfl_xor_sync(0xffffffffu, rv, o);
                int   oi = __shfl_xor_sync(0xffffffffu, ri, o);
                if (ov > rv || (ov == rv && oi < ri)) { rv = ov; ri = oi; }
            }
            rv = __shfl_sync(0xffffffffu, rv, 0);
            ri = __shfl_sync(0xffffffffu, ri, 0);
            if (lane < 8 && ri == hi) ptr++;
            if (lane == 0) {
                g_top[bh*UU + u] = ri;
                g_slot[bh*LL + ri] = u;
            }
        }
    }
}

// ---------------- K5: full scores from chunked keys, 10-u register blocked ----------------
__global__ void __launch_bounds__(512) k_scores()
{
    __shared__ float2 shq[10][EE];
    int bh = blockIdx.z;
    int ug = blockIdx.y;
    int jt = blockIdx.x;
    int tid = threadIdx.x;
    for (int t = tid; t < 10*EE; t += 512) {
        int ul = t / EE, e = t - ul*EE;
        int qi = g_top[bh*UU + ug*10 + ul];
        shq[ul][e] = g_qf[((size_t)bh*LL + qi)*EE + e];
    }
    __syncthreads();
    int j = jt*512 + tid;
    float accR[10], accI[10];
    #pragma unroll
    for (int u = 0; u < 10; ++u) { accR[u] = 0.f; accI[u] = 0.f; }
    const float4* kc = g_kfC + (((size_t)(bh*8)) << 12);
    #pragma unroll 1
    for (int c = 0; c < 8; ++c) {
        float4 h0 = kc[((size_t)c << 12) + j*2];
        float4 h1 = kc[((size_t)c << 12) + j*2 + 1];
        #pragma unroll
        for (int u = 0; u < 10; ++u) {
            float2 q0 = shq[u][4*c], q1 = shq[u][4*c+1], q2 = shq[u][4*c+2], q3 = shq[u][4*c+3];
            accR[u] = fmaf(q0.x, h0.x, accR[u]); accR[u] = fmaf(-q0.y, h0.y, accR[u]);
            accI[u] = fmaf(q0.x, h0.y, accI[u]); accI[u] = fmaf( q0.y, h0.x, accI[u]);
            accR[u] = fmaf(q1.x, h0.z, accR[u]); accR[u] = fmaf(-q1.y, h0.w, accR[u]);
            accI[u] = fmaf(q1.x, h0.w, accI[u]); accI[u] = fmaf( q1.y, h0.z, accI[u]);
            accR[u] = fmaf(q2.x, h1.x, accR[u]); accR[u] = fmaf(-q2.y, h1.y, accR[u]);
            accI[u] = fmaf(q2.x, h1.y, accI[u]); accI[u] = fmaf( q2.y, h1.x, accI[u]);
            accR[u] = fmaf(q3.x, h1.z, accR[u]); accR[u] = fmaf(-q3.y, h1.w, accR[u]);
            accI[u] = fmaf(q3.x, h1.w, accI[u]); accI[u] = fmaf( q3.y, h1.z, accI[u]);
        }
    }
    {
        float k32 = g_k32[bh*LL + j];
        #pragma unroll
        for (int u = 0; u < 10; ++u) {
            float2 qv = shq[u][32];
            accR[u] = fmaf(qv.x, k32, accR[u]);
            accI[u] = fmaf(qv.y, k32, accI[u]);
        }
    }
    const float sc = 0.125f;
    #pragma unroll
    for (int u = 0; u < 10; ++u)
        g_big[((size_t)bh*UU + ug*10 + u)*LL + j] = make_float2(accR[u]*sc, accI[u]*sc);
}

// ---------------- K6: fused softmax + upd (4 u per block, 2 blocks/SM) ----------------
#define SMU_SMEM (65536 + 16896 + 128)
__global__ void __launch_bounds__(512) k_smupd()
{
    extern __shared__ char smc[];
    float2* p    = (float2*)smc;
    float2* accs = (float2*)(smc + 65536);
    float2* mxs  = (float2*)(smc + 65536 + 16896);
    int bh = blockIdx.y, ug = blockIdx.x;
    int tid = threadIdx.x, warp = tid >> 5, lane = tid & 31;

    const float2* gb = g_big + ((size_t)bh*UU + ug*4)*LL;
    for (int i = tid; i < 4*LL; i += 512)
        p[i] = gb[i];
    __syncthreads();

    int su = warp >> 2, qt = warp & 3;
    float2* row = p + (su << 11) + (qt << 9);
    float mr = -3.4e38f, mi = -3.4e38f;
    #pragma unroll 8
    for (int k2 = 0; k2 < 16; ++k2) {
        float2 vv = row[lane + k2*32];
        mr = fmaxf(mr, vv.x); mi = fmaxf(mi, vv.y);
    }
    #pragma unroll
    for (int o = 16; o; o >>= 1) {
        mr = fmaxf(mr, __shfl_xor_sync(0xffffffffu, mr, o));
        mi = fmaxf(mi, __shfl_xor_sync(0xffffffffu, mi, o));
    }
    if (lane == 0) mxs[warp] = make_float2(mr, mi);
    __syncthreads();
    {
        float2 a = mxs[su*4], b = mxs[su*4+1], c = mxs[su*4+2], d = mxs[su*4+3];
        mr = fmaxf(fmaxf(a.x, b.x), fmaxf(c.x, d.x));
        mi = fmaxf(fmaxf(a.y, b.y), fmaxf(c.y, d.y));
    }
    __syncthreads();
    float sr = 0.f, si = 0.f;
    #pragma unroll 8
    for (int k2 = 0; k2 < 16; ++k2) {
        float2 vv = row[lane + k2*32];
        float er = __expf(vv.x - mr);
        float ei = __expf(vv.y - mi);
        row[lane + k2*32] = make_float2(er, ei);
        sr += er; si += ei;
    }
    #pragma unroll
    for (int o = 16; o; o >>= 1) {
        sr += __shfl_xor_sync(0xffffffffu, sr, o);
        si += __shfl_xor_sync(0xffffffffu, si, o);
    }
    if (lane == 0) mxs[warp] = make_float2(sr, si);
    __syncthreads();
    {
        float2 a = mxs[su*4], b = mxs[su*4+1], c = mxs[su*4+2], d = mxs[su*4+3];
        float inr = 1.0f / (a.x + b.x + c.x + d.x);
        float ini = 1.0f / (a.y + b.y + c.y + d.y);
        #pragma unroll 8
        for (int k2 = 0; k2 < 16; ++k2) {
            float2 vv = row[lane + k2*32];
            row[lane + k2*32] = make_float2(vv.x * inr, vv.y * ini);
        }
    }
    __syncthreads();

    float aR[4], aI[4];
    #pragma unroll
    for (int u = 0; u < 4; ++u) { aR[u]=0.f; aI[u]=0.f; }
    const float2* vb = g_vf + (size_t)bh*LL*EE;
    for (int l = warp; l < LL; l += 16) {
        float2 v2 = vb[(size_t)l*EE + lane];
        #pragma unroll
        for (int u = 0; u < 4; ++u) {
            float2 pp = p[(u << 11) + l];
            aR[u] = fmaf(pp.x, v2.x, aR[u]);
            aI[u] = fmaf(pp.y, v2.y, aI[u]);
        }
    }
    float s32[4];
    #pragma unroll
    for (int u = 0; u < 4; ++u) s32[u] = 0.f;
    for (int l = tid; l < LL; l += 512) {
        float v32r = vb[(size_t)l*EE + 32].x;
        #pragma unroll
        for (int u = 0; u < 4; ++u)
            s32[u] = fmaf(p[(u << 11) + l].x, v32r, s32[u]);
    }
    #pragma unroll
    for (int o = 16; o; o >>= 1) {
        #pragma unroll
        for (int u = 0; u < 4; ++u)
            s32[u] += __shfl_xor_sync(0xffffffffu, s32[u], o);
    }
    #pragma unroll
    for (int u = 0; u < 4; ++u) {
        accs[(warp*4 + u)*EE + lane] = make_float2(aR[u], aI[u]);
        if (lane == 0) accs[(warp*4 + u)*EE + 32] = make_float2(s32[u], 0.f);
    }
    __syncthreads();
    for (int t = tid; t < 4*EE; t += 512) {
        int u = t / EE, e = t - u*EE;
        float ssr = 0.f, ssi = 0.f;
        #pragma unroll
        for (int w = 0; w < 16; ++w) {
            float2 a = accs[(w*4 + u)*EE + e];
            ssr += a.x; ssi += a.y;
        }
        g_upd[((size_t)bh*UU + ug*4 + u)*EE + e] = make_float2(ssr, ssi);
    }
}

// ---------------- K7: scatter + irfft, 4 rows per warp ----------------
__global__ void k_out(float* __restrict__ out)
{
    __shared__ float tc[64], ts[64];
    __shared__ float2 ub[8][EE];
    int tid = threadIdx.x;
    if (tid < 64) {
        float s, c;
        sincospif(tid * (1.0f/32.0f), &s, &c);
        tc[tid] = c; ts[tid] = s;
    }
    __syncthreads();
    int warp = tid >> 5, lane = tid & 31;
    #pragma unroll 1
    for (int i = 0; i < 4; ++i) {
        int r = blockIdx.x * 32 + warp * 4 + i;
        int bh = r >> 11;
        int slot = g_slot[r];
        float* op = out + (size_t)r * DD;
        if (slot < 0) {
            op[lane]      = g_vmt[bh*DD + lane];
            op[lane + 32] = g_vmt[bh*DD + lane + 32];
        } else {
            const float2* X = g_upd + ((size_t)bh*UU + slot)*EE;
            ub[warp][lane] = X[lane];
            if (lane == 0) ub[warp][32] = X[32];
            __syncwarp();
            float a0 = ub[warp][0].x;
            float a32 = ub[warp][32].x;
            float sgn = (lane & 1) ? -a32 : a32;
            float acc1 = a0 + sgn, acc2 = a0 + sgn;
            #pragma unroll
            for (int e = 1; e < 32; ++e) {
                float2 Xe = ub[warp][e];
                int j1 = (e * lane) & 63;
                int j2 = (e * (lane + 32)) & 63;
                acc1 += 2.f * (Xe.x*tc[j1] - Xe.y*ts[j1]);
                acc2 += 2.f * (Xe.x*tc[j2] - Xe.y*ts[j2]);
            }
            op[lane]      = acc1 * (1.0f/64.0f);
            op[lane + 32] = acc2 * (1.0f/64.0f);
            __syncwarp();
        }
    }
}

// ---------------- launch ----------------
extern "C" void kernel_launch(void* const* d_in, const int* in_sizes, int n_in,
                              void* d_out, int out_size)
{
    (void)in_sizes; (void)n_in; (void)out_size;
    const float* q = (const float*)d_in[0];
    const float* k = (const float*)d_in[1];
    const float* v = (const float*)d_in[2];
    const int* isamp = (const int*)d_in[4];
    float* out = (float*)d_out;

    cudaFuncSetAttribute(k_msample, cudaFuncAttributeMaxDynamicSharedMemorySize, MS_SMEM);
    cudaFuncSetAttribute(k_smupd,   cudaFuncAttributeMaxDynamicSharedMemorySize, SMU_SMEM);

    k_rfft     <<<dim3(ROWS/32, 3), 256>>>(q, k, v);
    k_vmt      <<<BHN, 512>>>(v);
    k_msample  <<<dim3(LL/256, BHN), 1024, MS_SMEM>>>(isamp);
    k_topk     <<<BHN, 256>>>();
    k_scores   <<<dim3(4, 4, BHN), 512>>>();
    k_smupd    <<<dim3(10, BHN), 512, SMU_SMEM>>>();
    k_out      <<<ROWS/32, 256>>>(out);
}